// round 13
// baseline (speedup 1.0000x reference)
#include <cuda_runtime.h>
#include <cuda_fp16.h>
#include <cstdint>

#define BATCH 2048
#define ENS   32
#define DX    14
#define DZ    14
#define PM_IN 140
#define SM_IN 220
#define BE    (BATCH * ENS)

#define O1_OFF 0
#define O2_OFF (BATCH * ENS * DX)
#define O3_OFF (O2_OFF + BATCH * DX)
#define O4_OFF (O3_OFF + BATCH * DX)
#define O5_OFF (O4_OFF + BATCH * DZ)

// fused kernel smem layout
#define H1_OFF    0          // 4 boxes x 16KB = 65536 (h1 fp16, swizzled)
#define STG_OFF   65536      // 2 x 16KB streaming stages
#define BIASF_OFF 98304      // 512 floats (b1 phase1, b3 phase2)
#define WM2F_OFF  100352     // 128*14 floats = 7168
#define PROJ_OFF  107520     // 128*14 floats = 7168
#define FUSED_SMEM 114688

// ---------------- scratch globals (uint32 = packed fp16 pair) ----------------
__device__ uint32_t g_x [(size_t)BE * 96];     // x   fp16 [BE][192]
__device__ uint32_t g_w1[256 * 96];            // w1^T fp16 [256][192]
__device__ uint32_t g_w3[512 * 128];           // w3^T fp16 [512][256]
__device__ float    g_part[(size_t)BE * DX];   // single pred partial slice
__device__ float    g_sens[BATCH * DZ];

// ---------------- helpers ----------------
__device__ __forceinline__ uint32_t smem_u32(const void* p) {
    uint32_t a;
    asm("{ .reg .u64 t; cvta.to.shared.u64 t, %1; cvt.u32.u64 %0, t; }" : "=r"(a) : "l"(p));
    return a;
}
#define CP16(d, s) asm volatile("cp.async.cg.shared.global [%0], [%1], 16;" :: "r"(d), "l"(s))
#define CP_COMMIT() asm volatile("cp.async.commit_group;")
#define CP_WAITG(n) asm volatile("cp.async.wait_group %0;" :: "n"(n) : "memory")

__device__ __forceinline__ void ldsm4(uint32_t (&r)[4], uint32_t addr) {
    asm volatile("ldmatrix.sync.aligned.m8n8.x4.shared.b16 {%0,%1,%2,%3}, [%4];"
                 : "=r"(r[0]), "=r"(r[1]), "=r"(r[2]), "=r"(r[3]) : "r"(addr));
}
__device__ __forceinline__ void mma_f16(float (&d)[4], const uint32_t (&a)[4],
                                        uint32_t b0, uint32_t b1) {
    asm volatile(
        "mma.sync.aligned.m16n8k16.row.col.f32.f16.f16.f32 "
        "{%0,%1,%2,%3}, {%4,%5,%6,%7}, {%8,%9}, {%0,%1,%2,%3};"
        : "+f"(d[0]), "+f"(d[1]), "+f"(d[2]), "+f"(d[3])
        : "r"(a[0]), "r"(a[1]), "r"(a[2]), "r"(a[3]), "r"(b0), "r"(b1));
}
__device__ __forceinline__ uint32_t packA2(float v0, float v1) {
    __half h0 = __float2half_rn(v0), h1 = __float2half_rn(v1);
    return (uint32_t)__half_as_ushort(h0) | ((uint32_t)__half_as_ushort(h1) << 16);
}

// ---------------- prep: x -> fp16, K padded to 192 ----------------
__global__ void __launch_bounds__(256)
prep_x_kernel(const float* __restrict__ x)
{
    int idx = blockIdx.x * 256 + threadIdx.x;   // BE*96
    int row = idx / 96, p = idx % 96, k = 2 * p;
    float v0 = (k < PM_IN) ? x[(size_t)row * PM_IN + k] : 0.f;
    float v1 = (k + 1 < PM_IN) ? x[(size_t)row * PM_IN + k + 1] : 0.f;
    g_x[(size_t)row * 96 + p] = packA2(v0, v1);
}

// ---------------- prep: weights transposed -> fp16 ----------------
__global__ void __launch_bounds__(256)
prep_w_kernel(const float* __restrict__ w1, const float* __restrict__ w3)
{
    int idx = blockIdx.x * 256 + threadIdx.x;
    if (idx < 256 * 96) {                        // w1 [140][256] -> [256][192]
        int n = idx / 96, p = idx % 96, k = 2 * p;
        float v0 = (k < PM_IN) ? w1[(size_t)k * 256 + n] : 0.f;
        float v1 = (k + 1 < PM_IN) ? w1[(size_t)(k + 1) * 256 + n] : 0.f;
        g_w1[idx] = packA2(v0, v1);
    } else if (idx < 256 * 96 + 512 * 128) {     // w3 [256][512] -> [512][256]
        int i2 = idx - 256 * 96;
        int n = i2 / 128, p = i2 % 128, k = 2 * p;
        g_w3[i2] = packA2(w3[(size_t)k * 512 + n], w3[(size_t)(k + 1) * 512 + n]);
    }
}

// ---------------- Fused process-model kernel ------------------------------
// One CTA per 128-row block (grid 512), 256 threads, 8 warps (4m x 2n), 2 CTAs/SM.
// Phase 1: h1 = leaky(x @ w1 + b1) -> smem boxes (fp16, swizzled). N=256 in 2 halves.
// Phase 2: stream w3 slices; A = h1 from smem; fused wm2 projection accumulated
//          into smem proj buffer (atomicAdd: two n-half warps share rows).
__global__ void __launch_bounds__(256, 2)
fused_pm_kernel(const uint32_t* __restrict__ X, const uint32_t* __restrict__ W1,
                const uint32_t* __restrict__ W3,
                const float* __restrict__ b1, const float* __restrict__ b3,
                const float* __restrict__ wm2, float* __restrict__ part)
{
    extern __shared__ char smem[];
    const uint32_t ub = smem_u32(smem);
    float* biasS = (float*)(smem + BIASF_OFF);
    float* wm2s  = (float*)(smem + WM2F_OFF);
    float* projS = (float*)(smem + PROJ_OFF);

    const int tid = threadIdx.x, wid = tid >> 5, lane = tid & 31;
    const int bt = blockIdx.x;
    const int mw = (wid >> 1) * 32;              // 4 m-groups
    const int nw = (wid & 1) * 64;               // 2 n-groups

    if (tid < 256) biasS[tid] = b1[tid];
    for (int i = tid; i < 128 * DX; i += 256) projS[i] = 0.f;

    float acc[2][8][4];

    // ===================== Phase 1: h1 into smem =====================
    for (int bn2 = 0; bn2 < 2; bn2++) {
#pragma unroll
        for (int f = 0; f < 2; f++)
#pragma unroll
            for (int g = 0; g < 8; g++)
#pragma unroll
                for (int e = 0; e < 4; e++) acc[f][g][e] = 0.f;

#pragma unroll 1
        for (int kc = 0; kc < 3; kc++) {
            // load x box kc -> stage0, w1 box -> stage1 (2048 units, 8/thread)
#pragma unroll
            for (int q = 0; q < 8; q++) {
                int i = tid + 256 * q;
                int t = i >> 10, r = (i >> 3) & 127, c = i & 7;
                const uint32_t* src = t
                    ? W1 + (size_t)(bn2 * 128 + r) * 96 + kc * 32 + c * 4
                    : X  + (size_t)(bt * 128 + r) * 96 + kc * 32 + c * 4;
                uint32_t dst = ub + STG_OFF + t * 16384 + r * 128
                             + ((c * 16) ^ ((r & 7) << 4));
                CP16(dst, src);
            }
            CP_COMMIT();
            CP_WAITG(0);
            __syncthreads();

#pragma unroll
            for (int k16 = 0; k16 < 4; k16++) {
                uint32_t ah[2][4];
#pragma unroll
                for (int f = 0; f < 2; f++) {
                    int mrow = mw + f * 16 + (lane & 15);
                    int cb = k16 * 32 + ((lane >> 4) << 4);
                    uint32_t off = mrow * 128 + (cb ^ ((mrow & 7) << 4));
                    ldsm4(ah[f], ub + STG_OFF + off);
                }
                uint32_t bh[4][4];
#pragma unroll
                for (int g = 0; g < 4; g++) {
                    int nrow = nw + g * 16 + ((lane >> 4) << 3) + (lane & 7);
                    int cb = k16 * 32 + (((lane >> 3) & 1) << 4);
                    uint32_t off = nrow * 128 + (cb ^ ((nrow & 7) << 4));
                    ldsm4(bh[g], ub + STG_OFF + 16384 + off);
                }
#pragma unroll
                for (int f = 0; f < 2; f++)
#pragma unroll
                    for (int g = 0; g < 4; g++) {
                        mma_f16(acc[f][2 * g],     ah[f], bh[g][0], bh[g][1]);
                        mma_f16(acc[f][2 * g + 1], ah[f], bh[g][2], bh[g][3]);
                    }
            }
            __syncthreads();
        }

        // epilogue: h1 = leaky(acc + b1) -> smem boxes (same swizzle as loads)
#pragma unroll
        for (int f = 0; f < 2; f++) {
            int r0 = mw + f * 16 + (lane >> 2);
#pragma unroll
            for (int nf = 0; nf < 8; nf++) {
                int col = nw + nf * 8 + 2 * (lane & 3);
                int gc  = bn2 * 128 + col;
                float bb0 = biasS[gc], bb1 = biasS[gc + 1];
                float v0 = acc[f][nf][0] + bb0, v1 = acc[f][nf][1] + bb1;
                float v2 = acc[f][nf][2] + bb0, v3 = acc[f][nf][3] + bb1;
                v0 = v0 >= 0.f ? v0 : 0.01f * v0;
                v1 = v1 >= 0.f ? v1 : 0.01f * v1;
                v2 = v2 >= 0.f ? v2 : 0.01f * v2;
                v3 = v3 >= 0.f ? v3 : 0.01f * v3;
                int box = gc >> 6, cb2 = (gc & 63) * 2;
                uint32_t base = ub + H1_OFF + box * 16384;
                uint32_t a0 = base + r0 * 128 + (cb2 ^ ((r0 & 7) << 4));
                uint32_t a1 = base + (r0 + 8) * 128 + (cb2 ^ (((r0 + 8) & 7) << 4));
                uint32_t p0 = packA2(v0, v1), p1 = packA2(v2, v3);
                asm volatile("st.shared.b32 [%0], %1;" :: "r"(a0), "r"(p0) : "memory");
                asm volatile("st.shared.b32 [%0], %1;" :: "r"(a1), "r"(p1) : "memory");
            }
        }
        __syncthreads();
    }

    // load b3 (512 floats) after phase1 done with b1
    if (tid < 256) { biasS[tid] = b3[tid]; biasS[256 + tid] = b3[256 + tid]; }
    __syncthreads();

    // ===================== Phase 2: h2 projection =====================
    for (int bn2 = 0; bn2 < 4; bn2++) {
        // wm2 slice for this bn2
        for (int i = tid; i < 128 * DX; i += 256) {
            int c = i / DX, m = i % DX;
            wm2s[c * DX + m] = wm2[(size_t)(bn2 * 128 + c) * DX + m];
        }
#pragma unroll
        for (int f = 0; f < 2; f++)
#pragma unroll
            for (int g = 0; g < 8; g++)
#pragma unroll
                for (int e = 0; e < 4; e++) acc[f][g][e] = 0.f;

        // prefetch w3 boxes 0,1 (1024 units each, 4/thread)
        auto issue_w3 = [&](int stage, int kc) {
#pragma unroll
            for (int q = 0; q < 4; q++) {
                int i = tid + 256 * q;
                int r = i >> 3, c = i & 7;
                const uint32_t* src = W3 + (size_t)(bn2 * 128 + r) * 128 + kc * 32 + c * 4;
                uint32_t dst = ub + STG_OFF + stage * 16384 + r * 128
                             + ((c * 16) ^ ((r & 7) << 4));
                CP16(dst, src);
            }
            CP_COMMIT();
        };
        issue_w3(0, 0);
        issue_w3(1, 1);

#pragma unroll 1
        for (int kc = 0; kc < 4; kc++) {
            if (kc + 1 < 4) { CP_WAITG(1); } else { CP_WAITG(0); }
            __syncthreads();

            const uint32_t sa  = ub + H1_OFF + kc * 16384;          // A = h1 box
            const uint32_t sbb = ub + STG_OFF + (kc & 1) * 16384;   // B = w3 stage
#pragma unroll
            for (int k16 = 0; k16 < 4; k16++) {
                uint32_t ah[2][4];
#pragma unroll
                for (int f = 0; f < 2; f++) {
                    int mrow = mw + f * 16 + (lane & 15);
                    int cb = k16 * 32 + ((lane >> 4) << 4);
                    uint32_t off = mrow * 128 + (cb ^ ((mrow & 7) << 4));
                    ldsm4(ah[f], sa + off);
                }
                uint32_t bh[4][4];
#pragma unroll
                for (int g = 0; g < 4; g++) {
                    int nrow = nw + g * 16 + ((lane >> 4) << 3) + (lane & 7);
                    int cb = k16 * 32 + (((lane >> 3) & 1) << 4);
                    uint32_t off = nrow * 128 + (cb ^ ((nrow & 7) << 4));
                    ldsm4(bh[g], sbb + off);
                }
#pragma unroll
                for (int f = 0; f < 2; f++)
#pragma unroll
                    for (int g = 0; g < 4; g++) {
                        mma_f16(acc[f][2 * g],     ah[f], bh[g][0], bh[g][1]);
                        mma_f16(acc[f][2 * g + 1], ah[f], bh[g][2], bh[g][3]);
                    }
            }
            __syncthreads();
            if (kc + 2 < 4) issue_w3(kc & 1, kc + 2);
        }

        // epilogue: project leaky(acc + b3) onto wm2 slice.
        // Two n-half warps share the same rows -> atomicAdd into projS.
#pragma unroll
        for (int f = 0; f < 2; f++) {
            float p0[DX], p1[DX];
#pragma unroll
            for (int m = 0; m < DX; m++) { p0[m] = 0.f; p1[m] = 0.f; }
#pragma unroll
            for (int nf = 0; nf < 8; nf++) {
                int col = nw + nf * 8 + 2 * (lane & 3);
#pragma unroll
                for (int e = 0; e < 2; e++) {
                    int c = col + e;
                    float b = biasS[bn2 * 128 + c];
                    float v0 = acc[f][nf][e] + b;
                    float v1 = acc[f][nf][2 + e] + b;
                    v0 = v0 >= 0.f ? v0 : 0.01f * v0;
                    v1 = v1 >= 0.f ? v1 : 0.01f * v1;
                    const float* wr = wm2s + c * DX;
#pragma unroll
                    for (int m = 0; m < DX; m++) {
                        float wv = wr[m];
                        p0[m] += v0 * wv;
                        p1[m] += v1 * wv;
                    }
                }
            }
#pragma unroll
            for (int m = 0; m < DX; m++) {
                p0[m] += __shfl_xor_sync(0xFFFFFFFFu, p0[m], 1);
                p0[m] += __shfl_xor_sync(0xFFFFFFFFu, p0[m], 2);
                p1[m] += __shfl_xor_sync(0xFFFFFFFFu, p1[m], 1);
                p1[m] += __shfl_xor_sync(0xFFFFFFFFu, p1[m], 2);
            }
            if ((lane & 3) == 0) {
                int r0 = mw + f * 16 + (lane >> 2);
#pragma unroll
                for (int m = 0; m < DX; m++) {
                    atomicAdd(&projS[r0 * DX + m],       p0[m]);
                    atomicAdd(&projS[(r0 + 8) * DX + m], p1[m]);
                }
            }
        }
        __syncthreads();   // projS/wm2s safe for next bn2
    }

    // write pred partial
    for (int i = tid; i < 128 * DX; i += 256)
        part[(size_t)(bt * 128 + i / DX) * DX + i % DX] = projS[i];
}

// ---------------- sensor MLP on 2048 distinct rows ----------------
__global__ void __launch_bounds__(256)
sensor_kernel(const float* __restrict__ raw,
              const float* __restrict__ w2, const float* __restrict__ b2,
              const float* __restrict__ w3, const float* __restrict__ b3,
              const float* __restrict__ w5, const float* __restrict__ b5,
              const float* __restrict__ w6, const float* __restrict__ b6,
              float* __restrict__ sens)
{
    __shared__ float s[4][SM_IN], h1[4][256], h2[4][256], h3[4][64];
    const int tid = threadIdx.x;
    const int row0 = blockIdx.x * 4;

    for (int i = tid; i < 4 * SM_IN; i += 256)
        s[i / SM_IN][i % SM_IN] = raw[(size_t)(row0 + i / SM_IN) * SM_IN + i % SM_IN];
    __syncthreads();
    {
        float acc[4];
#pragma unroll
        for (int r = 0; r < 4; r++) acc[r] = b2[tid];
        for (int k = 0; k < SM_IN; k++) {
            float w = w2[k * 256 + tid];
#pragma unroll
            for (int r = 0; r < 4; r++) acc[r] += s[r][k] * w;
        }
#pragma unroll
        for (int r = 0; r < 4; r++) h1[r][tid] = acc[r] >= 0.f ? acc[r] : 0.01f * acc[r];
    }
    __syncthreads();
    {
        float acc[4];
#pragma unroll
        for (int r = 0; r < 4; r++) acc[r] = b3[tid];
        for (int k = 0; k < 256; k++) {
            float w = w3[k * 256 + tid];
#pragma unroll
            for (int r = 0; r < 4; r++) acc[r] += h1[r][k] * w;
        }
#pragma unroll
        for (int r = 0; r < 4; r++) h2[r][tid] = acc[r] >= 0.f ? acc[r] : 0.01f * acc[r];
    }
    __syncthreads();
    if (tid < 64) {
        float acc[4];
#pragma unroll
        for (int r = 0; r < 4; r++) acc[r] = b5[tid];
        for (int k = 0; k < 256; k++) {
            float w = w5[k * 64 + tid];
#pragma unroll
            for (int r = 0; r < 4; r++) acc[r] += h2[r][k] * w;
        }
#pragma unroll
        for (int r = 0; r < 4; r++) h3[r][tid] = acc[r] >= 0.f ? acc[r] : 0.01f * acc[r];
    }
    __syncthreads();
    if (tid < DZ) {
        float acc[4];
#pragma unroll
        for (int r = 0; r < 4; r++) acc[r] = b6[tid];
        for (int k = 0; k < 64; k++) {
            float w = w6[k * DZ + tid];
#pragma unroll
            for (int r = 0; r < 4; r++) acc[r] += h3[r][k] * w;
        }
#pragma unroll
        for (int r = 0; r < 4; r++) sens[(size_t)(row0 + r) * DZ + tid] = acc[r];
    }
}

// ---------------- EnKF per batch element ----------------
__global__ void __launch_bounds__(256)
enkf_kernel(const float* __restrict__ part, const float* __restrict__ pm_bm2,
            const float* __restrict__ sens,
            const float* __restrict__ on_w1, const float* __restrict__ on_b1,
            const float* __restrict__ on_w2, const float* __restrict__ on_b2,
            float* __restrict__ out1, float* __restrict__ out2,
            float* __restrict__ out3, float* __restrict__ out4,
            float* __restrict__ out5)
{
    const int b = blockIdx.x, tid = threadIdx.x;
    __shared__ float pred[ENS][DX], ez[ENS][DZ], Am[ENS][DX], corr[ENS][DX];
    __shared__ float sm[DX], zm[DZ], rdiag[DZ], hid[32];
    __shared__ float Mm[DX][DX], Km[DX][DZ], aug[DX][2 * DX], fac[DX];

    for (int i = tid; i < ENS * DX; i += 256) {
        int e = i / DX, j = i % DX;
        size_t row = (size_t)b * ENS + e;
        pred[e][j] = pm_bm2[j] + part[row * DX + j];
    }
    for (int i = tid; i < ENS * DZ; i += 256) {
        int e = i / DZ, j = i % DZ;
        int src = (b * ENS + e) % BATCH;
        float v = sens[src * DZ + j];
        ez[e][j] = v;
        out5[(size_t)(b * ENS + e) * DZ + j] = v;
    }
    __syncthreads();
    if (tid < DX) {
        float s1 = 0.f, s2 = 0.f;
        for (int e = 0; e < ENS; e++) { s1 += pred[e][tid]; s2 += ez[e][tid]; }
        float m1 = s1 * (1.f / ENS), m2 = s2 * (1.f / ENS);
        sm[tid] = m1; zm[tid] = m2;
        out3[b * DX + tid] = m1;
        out4[b * DZ + tid] = m2;
    }
    __syncthreads();
    if (tid < 32) {
        float a = on_b1[tid];
        for (int i = 0; i < DZ; i++) a += zm[i] * on_w1[i * 32 + tid];
        hid[tid] = a > 0.f ? a : 0.f;
    }
    __syncthreads();
    if (tid < DZ) {
        float a = on_b2[tid];
        for (int j = 0; j < 32; j++) a += hid[j] * on_w2[j * DZ + tid];
        a += 0.001f;
        rdiag[tid] = a * a + 0.038729833f;
    }
    for (int i = tid; i < ENS * DX; i += 256)
        Am[i / DX][i % DX] = pred[i / DX][i % DX] - sm[i % DX];
    __syncthreads();
    if (tid < DX * DX) {
        int i = tid / DX, j = tid % DX;
        float s = 0.f;
        for (int e = 0; e < ENS; e++) s += Am[e][i] * Am[e][j];
        float m = s * (1.f / (ENS - 1));
        Mm[i][j] = m;
        aug[i][j] = m + (i == j ? rdiag[i] : 0.f);
        aug[i][DX + j] = (i == j) ? 1.f : 0.f;
    }
    __syncthreads();
    for (int p = 0; p < DX; p++) {
        float pv = aug[p][p];
        __syncthreads();
        if (tid < 2 * DX) aug[p][tid] *= (1.f / pv);
        if (tid < DX) fac[tid] = (tid == p) ? 0.f : aug[tid][p];
        __syncthreads();
        for (int t = tid; t < DX * 2 * DX; t += 256) {
            int rr = t / (2 * DX), c = t % (2 * DX);
            if (rr != p) aug[rr][c] -= fac[rr] * aug[p][c];
        }
        __syncthreads();
    }
    if (tid < DX * DX) {
        int i = tid / DX, j = tid % DX;
        float s = 0.f;
        for (int k = 0; k < DX; k++) s += Mm[i][k] * aug[k][DX + j];
        Km[i][j] = s;
    }
    __syncthreads();
    for (int t = tid; t < ENS * DX; t += 256) {
        int e = t / DX, i = t % DX;
        float s = pred[e][i];
        for (int j = 0; j < DZ; j++) s += Km[i][j] * (ez[e][j] - pred[e][j]);
        corr[e][i] = s;
        out1[(size_t)(b * ENS + e) * DX + i] = s;
    }
    __syncthreads();
    if (tid < DX) {
        float s = 0.f;
        for (int e = 0; e < ENS; e++) s += corr[e][tid];
        out2[b * DX + tid] = s * (1.f / ENS);
    }
}

// ---------------- launcher ----------------
extern "C" void kernel_launch(void* const* d_in, const int* in_sizes, int n_in,
                              void* d_out, int out_size)
{
    const float* raw    = (const float*)d_in[0];
    const float* sp     = (const float*)d_in[1];
    const float* pm_w1  = (const float*)d_in[2];
    const float* pm_b1  = (const float*)d_in[3];
    const float* pm_w3  = (const float*)d_in[4];
    const float* pm_b3  = (const float*)d_in[5];
    const float* pm_wm2 = (const float*)d_in[6];
    const float* pm_bm2 = (const float*)d_in[7];
    const float* sm_w2  = (const float*)d_in[8];
    const float* sm_b2  = (const float*)d_in[9];
    const float* sm_w3  = (const float*)d_in[10];
    const float* sm_b3  = (const float*)d_in[11];
    const float* sm_w5  = (const float*)d_in[12];
    const float* sm_b5  = (const float*)d_in[13];
    const float* sm_w6  = (const float*)d_in[14];
    const float* sm_b6  = (const float*)d_in[15];
    const float* on_w1  = (const float*)d_in[16];
    const float* on_b1  = (const float*)d_in[17];
    const float* on_w2  = (const float*)d_in[18];
    const float* on_b2  = (const float*)d_in[19];

    float* out = (float*)d_out;

    uint32_t *xp, *w1p, *w3p;
    float *partp, *sensp;
    cudaGetSymbolAddress((void**)&xp,  g_x);
    cudaGetSymbolAddress((void**)&w1p, g_w1);
    cudaGetSymbolAddress((void**)&w3p, g_w3);
    cudaGetSymbolAddress((void**)&partp, g_part);
    cudaGetSymbolAddress((void**)&sensp, g_sens);

    cudaFuncSetAttribute(fused_pm_kernel, cudaFuncAttributeMaxDynamicSharedMemorySize, FUSED_SMEM);

    prep_w_kernel<<<(256 * 96 + 512 * 128 + 255) / 256, 256>>>(pm_w1, pm_w3);
    prep_x_kernel<<<BE * 96 / 256, 256>>>(sp);

    fused_pm_kernel<<<BE / 128, 256, FUSED_SMEM>>>(xp, w1p, w3p, pm_b1, pm_b3,
                                                   pm_wm2, partp);

    sensor_kernel<<<BATCH / 4, 256>>>(raw, sm_w2, sm_b2, sm_w3, sm_b3,
                                      sm_w5, sm_b5, sm_w6, sm_b6, sensp);
    enkf_kernel<<<BATCH, 256>>>(partp, pm_bm2, sensp, on_w1, on_b1, on_w2, on_b2,
                                out + O1_OFF, out + O2_OFF, out + O3_OFF,
                                out + O4_OFF, out + O5_OFF);
}

// round 14
// speedup vs baseline: 1.2619x; 1.2619x over previous
#include <cuda_runtime.h>
#include <cuda_fp16.h>
#include <cstdint>

#define BATCH 2048
#define ENS   32
#define DX    14
#define DZ    14
#define PM_IN 140
#define SM_IN 220
#define BE    (BATCH * ENS)

#define O1_OFF 0
#define O2_OFF (BATCH * ENS * DX)
#define O3_OFF (O2_OFF + BATCH * DX)
#define O4_OFF (O3_OFF + BATCH * DX)
#define O5_OFF (O4_OFF + BATCH * DZ)

// smem layout (per CTA): 3 stages x 32KB tiles, then bias, then wm2 slice
#define STAGE_BYTES 32768
#define BIAS_OFF    98304
#define WM2_OFF     98816
#define DYN_SMEM    107008

// ---------------- scratch globals (uint32 = packed fp16 pair) ----------------
__device__ uint32_t g_x [(size_t)BE * 96];     // x   fp16 [BE][192]
__device__ uint32_t g_w1[256 * 96];            // w1^T fp16 [256][192]
__device__ uint32_t g_w3[512 * 128];           // w3^T fp16 [512][256]
__device__ uint32_t g_h1[(size_t)BE * 128];    // h1  fp16 [BE][256]
__device__ float    g_part[(size_t)8 * BE * DX];   // 8 partial slices
__device__ float    g_sens[BATCH * DZ];

// ---------------- helpers ----------------
__device__ __forceinline__ uint32_t smem_u32(const void* p) {
    uint32_t a;
    asm("{ .reg .u64 t; cvta.to.shared.u64 t, %1; cvt.u32.u64 %0, t; }" : "=r"(a) : "l"(p));
    return a;
}
#define CP16(d, s) asm volatile("cp.async.cg.shared.global [%0], [%1], 16;" :: "r"(d), "l"(s))
#define CP_COMMIT() asm volatile("cp.async.commit_group;")
#define CP_WAITG(n) asm volatile("cp.async.wait_group %0;" :: "n"(n) : "memory")

__device__ __forceinline__ void ldsm4(uint32_t (&r)[4], uint32_t addr) {
    asm volatile("ldmatrix.sync.aligned.m8n8.x4.shared.b16 {%0,%1,%2,%3}, [%4];"
                 : "=r"(r[0]), "=r"(r[1]), "=r"(r[2]), "=r"(r[3]) : "r"(addr));
}
__device__ __forceinline__ void mma_f16(float (&d)[4], const uint32_t (&a)[4],
                                        uint32_t b0, uint32_t b1) {
    asm volatile(
        "mma.sync.aligned.m16n8k16.row.col.f32.f16.f16.f32 "
        "{%0,%1,%2,%3}, {%4,%5,%6,%7}, {%8,%9}, {%0,%1,%2,%3};"
        : "+f"(d[0]), "+f"(d[1]), "+f"(d[2]), "+f"(d[3])
        : "r"(a[0]), "r"(a[1]), "r"(a[2]), "r"(a[3]), "r"(b0), "r"(b1));
}
__device__ __forceinline__ uint32_t packA2(float v0, float v1) {
    __half h0 = __float2half_rn(v0), h1 = __float2half_rn(v1);
    return (uint32_t)__half_as_ushort(h0) | ((uint32_t)__half_as_ushort(h1) << 16);
}

// ---------------- prep: x -> fp16, K padded to 192 ----------------
__global__ void __launch_bounds__(256)
prep_x_kernel(const float* __restrict__ x)
{
    int idx = blockIdx.x * 256 + threadIdx.x;   // BE*96
    int row = idx / 96, p = idx % 96, k = 2 * p;
    float v0 = (k < PM_IN) ? x[(size_t)row * PM_IN + k] : 0.f;
    float v1 = (k + 1 < PM_IN) ? x[(size_t)row * PM_IN + k + 1] : 0.f;
    g_x[(size_t)row * 96 + p] = packA2(v0, v1);
}

// ---------------- prep: weights transposed -> fp16 ----------------
__global__ void __launch_bounds__(256)
prep_w_kernel(const float* __restrict__ w1, const float* __restrict__ w3)
{
    int idx = blockIdx.x * 256 + threadIdx.x;
    if (idx < 256 * 96) {                        // w1 [140][256] -> [256][192]
        int n = idx / 96, p = idx % 96, k = 2 * p;
        float v0 = (k < PM_IN) ? w1[(size_t)k * 256 + n] : 0.f;
        float v1 = (k + 1 < PM_IN) ? w1[(size_t)(k + 1) * 256 + n] : 0.f;
        g_w1[idx] = packA2(v0, v1);
    } else if (idx < 256 * 96 + 512 * 128) {     // w3 [256][512] -> [512][256]
        int i2 = idx - 256 * 96;
        int n = i2 / 128, p = i2 % 128, k = 2 * p;
        g_w3[i2] = packA2(w3[(size_t)k * 512 + n], w3[(size_t)(k + 1) * 512 + n]);
    }
}

// ---------------- HMMA fp16 GEMM: 8 warps, 2 CTAs/SM, 3-stage pipeline -----
// CTA tile 128x128, BK=64, 8 warps (4m x 2n), warp tile 32x64.  (R10 proven)
template <int KCHUNKS, int EPI>
__global__ void __launch_bounds__(256, 2)
gemm_hmma(const uint32_t* __restrict__ A, const uint32_t* __restrict__ B,
          int kstr, const float* __restrict__ bias, const float* __restrict__ wm2)
{
    extern __shared__ char smem[];
    const uint32_t ub = smem_u32(smem);
    float* biasS = (float*)(smem + BIAS_OFF);
    float* wm2s  = (float*)(smem + WM2_OFF);

    const int tid = threadIdx.x, wid = tid >> 5, lane = tid & 31;
    const int bn = blockIdx.x, bt = blockIdx.y;
    const int mw = (wid >> 1) * 32;
    const int nw = (wid & 1) * 64;

    if (tid < 128) biasS[tid] = bias[bn * 128 + tid];
    if (EPI == 1) {
        for (int i = tid; i < 128 * DX; i += 256) {
            int c = i / DX, m = i % DX;
            wm2s[c * 16 + m] = wm2[(size_t)(bn * 128 + c) * DX + m];
        }
    }

    auto issue_load = [&](int stage, int kc) {
        const uint32_t sb = ub + stage * STAGE_BYTES;
#pragma unroll
        for (int q = 0; q < 8; q++) {
            int i = tid + 256 * q;
            int t = i >> 10, r = (i >> 3) & 127, c = i & 7;
            const uint32_t* gp = t ? B : A;
            int grow = (t ? bn : bt) * 128 + r;
            const uint32_t* src = gp + (size_t)grow * kstr + kc * 32 + c * 4;
            uint32_t dst = sb + t * 16384 + r * 128 + ((c * 16) ^ ((r & 7) << 4));
            CP16(dst, src);
        }
        CP_COMMIT();
    };

    float acc[2][8][4];
#pragma unroll
    for (int f = 0; f < 2; f++)
#pragma unroll
        for (int g = 0; g < 8; g++)
#pragma unroll
            for (int e = 0; e < 4; e++) acc[f][g][e] = 0.f;

    issue_load(0, 0);
    if (KCHUNKS > 1) issue_load(1, 1);

#pragma unroll 1
    for (int kc = 0; kc < KCHUNKS; kc++) {
        if (kc + 2 < KCHUNKS) {
            issue_load((kc + 2) % 3, kc + 2);
            CP_WAITG(2);
        } else if (kc + 1 < KCHUNKS) {
            CP_WAITG(1);
        } else {
            CP_WAITG(0);
        }
        __syncthreads();

        const uint32_t sb = ub + (kc % 3) * STAGE_BYTES;
#pragma unroll
        for (int k16 = 0; k16 < 4; k16++) {
            uint32_t ah[2][4];
#pragma unroll
            for (int f = 0; f < 2; f++) {
                int mrow = mw + f * 16 + (lane & 15);
                int cb = k16 * 32 + ((lane >> 4) << 4);
                uint32_t off = mrow * 128 + (cb ^ ((mrow & 7) << 4));
                ldsm4(ah[f], sb + off);
            }
            uint32_t bh[4][4];
#pragma unroll
            for (int g = 0; g < 4; g++) {
                int nrow = nw + g * 16 + ((lane >> 4) << 3) + (lane & 7);
                int cb = k16 * 32 + (((lane >> 3) & 1) << 4);
                uint32_t off = nrow * 128 + (cb ^ ((nrow & 7) << 4));
                ldsm4(bh[g], sb + 16384 + off);
            }
#pragma unroll
            for (int f = 0; f < 2; f++)
#pragma unroll
                for (int g = 0; g < 4; g++) {
                    mma_f16(acc[f][2 * g],     ah[f], bh[g][0], bh[g][1]);
                    mma_f16(acc[f][2 * g + 1], ah[f], bh[g][2], bh[g][3]);
                }
        }
        __syncthreads();
    }

    if (EPI == 0) {
#pragma unroll
        for (int f = 0; f < 2; f++) {
            int row0 = bt * 128 + mw + f * 16 + (lane >> 2);
#pragma unroll
            for (int nf = 0; nf < 8; nf++) {
                int col = nw + nf * 8 + 2 * (lane & 3);
                float b0 = biasS[col], b1 = biasS[col + 1];
                float v0 = acc[f][nf][0] + b0, v1 = acc[f][nf][1] + b1;
                float v2 = acc[f][nf][2] + b0, v3 = acc[f][nf][3] + b1;
                v0 = v0 >= 0.f ? v0 : 0.01f * v0;
                v1 = v1 >= 0.f ? v1 : 0.01f * v1;
                v2 = v2 >= 0.f ? v2 : 0.01f * v2;
                v3 = v3 >= 0.f ? v3 : 0.01f * v3;
                int gcol = bn * 128 + col;
                g_h1[(size_t)row0 * 128 + gcol / 2]       = packA2(v0, v1);
                g_h1[(size_t)(row0 + 8) * 128 + gcol / 2] = packA2(v2, v3);
            }
        }
    } else {
        float proj[4][DX];
#pragma unroll
        for (int s2 = 0; s2 < 4; s2++)
#pragma unroll
            for (int m = 0; m < DX; m++) proj[s2][m] = 0.f;
#pragma unroll
        for (int f = 0; f < 2; f++)
#pragma unroll
            for (int nf = 0; nf < 8; nf++) {
                int col = nw + nf * 8 + 2 * (lane & 3);
#pragma unroll
                for (int e = 0; e < 2; e++) {
                    int c = col + e;
                    float b = biasS[c];
                    float v0 = acc[f][nf][e] + b;
                    float v1 = acc[f][nf][2 + e] + b;
                    v0 = v0 >= 0.f ? v0 : 0.01f * v0;
                    v1 = v1 >= 0.f ? v1 : 0.01f * v1;
                    const float* wr = wm2s + c * 16;
#pragma unroll
                    for (int m = 0; m < DX; m++) {
                        float wv = wr[m];
                        proj[2 * f][m]     += v0 * wv;
                        proj[2 * f + 1][m] += v1 * wv;
                    }
                }
            }
#pragma unroll
        for (int s2 = 0; s2 < 4; s2++)
#pragma unroll
            for (int m = 0; m < DX; m++) {
                proj[s2][m] += __shfl_xor_sync(0xFFFFFFFFu, proj[s2][m], 1);
                proj[s2][m] += __shfl_xor_sync(0xFFFFFFFFu, proj[s2][m], 2);
            }
        if ((lane & 3) == 0) {
            int slice = bn * 2 + (wid & 1);
#pragma unroll
            for (int s2 = 0; s2 < 4; s2++) {
                int row = bt * 128 + mw + (s2 >> 1) * 16 + (lane >> 2) + (s2 & 1) * 8;
                float* dst = g_part + ((size_t)slice * BE + row) * DX;
#pragma unroll
                for (int m = 0; m < DX; m++) dst[m] = proj[s2][m];
            }
        }
    }
}

// ---------------- sensor MLP: 16 rows/block, smem aliasing, unrolled ------
#define SROWS 16
__global__ void __launch_bounds__(256)
sensor_kernel(const float* __restrict__ raw,
              const float* __restrict__ w2, const float* __restrict__ b2,
              const float* __restrict__ w3, const float* __restrict__ b3,
              const float* __restrict__ w5, const float* __restrict__ b5,
              const float* __restrict__ w6, const float* __restrict__ b6,
              float* __restrict__ sens)
{
    __shared__ float bufA[SROWS * 256];   // layer1 input (stride 220), later h2 (stride 256)
    __shared__ float h1s [SROWS * 256];
    __shared__ float h3s [SROWS * 64];
    const int tid = threadIdx.x;
    const int row0 = blockIdx.x * SROWS;

    for (int i = tid; i < SROWS * SM_IN; i += 256) {
        int r = i / SM_IN, k = i % SM_IN;
        bufA[r * SM_IN + k] = raw[(size_t)(row0 + r) * SM_IN + k];
    }
    __syncthreads();

    float acc[SROWS];
    {   // layer 1: 220 -> 256, leaky
#pragma unroll
        for (int r = 0; r < SROWS; r++) acc[r] = b2[tid];
#pragma unroll 4
        for (int k = 0; k < SM_IN; k++) {
            float w = w2[k * 256 + tid];
#pragma unroll
            for (int r = 0; r < SROWS; r++) acc[r] += bufA[r * SM_IN + k] * w;
        }
#pragma unroll
        for (int r = 0; r < SROWS; r++)
            h1s[r * 256 + tid] = acc[r] >= 0.f ? acc[r] : 0.01f * acc[r];
    }
    __syncthreads();
    {   // layer 2: 256 -> 256, leaky (output into bufA, stride 256)
#pragma unroll
        for (int r = 0; r < SROWS; r++) acc[r] = b3[tid];
#pragma unroll 4
        for (int k = 0; k < 256; k++) {
            float w = w3[k * 256 + tid];
#pragma unroll
            for (int r = 0; r < SROWS; r++) acc[r] += h1s[r * 256 + k] * w;
        }
        __syncthreads();   // everyone done reading bufA-as-s (layer1) long ago; h1 reads done
#pragma unroll
        for (int r = 0; r < SROWS; r++)
            bufA[r * 256 + tid] = acc[r] >= 0.f ? acc[r] : 0.01f * acc[r];
    }
    __syncthreads();
    if (tid < 64) {   // layer 3: 256 -> 64, leaky
#pragma unroll
        for (int r = 0; r < SROWS; r++) acc[r] = b5[tid];
#pragma unroll 4
        for (int k = 0; k < 256; k++) {
            float w = w5[k * 64 + tid];
#pragma unroll
            for (int r = 0; r < SROWS; r++) acc[r] += bufA[r * 256 + k] * w;
        }
#pragma unroll
        for (int r = 0; r < SROWS; r++)
            h3s[r * 64 + tid] = acc[r] >= 0.f ? acc[r] : 0.01f * acc[r];
    }
    __syncthreads();
    if (tid < DZ) {   // layer 4: 64 -> 14, linear
#pragma unroll
        for (int r = 0; r < SROWS; r++) acc[r] = b6[tid];
#pragma unroll 4
        for (int k = 0; k < 64; k++) {
            float w = w6[k * DZ + tid];
#pragma unroll
            for (int r = 0; r < SROWS; r++) acc[r] += h3s[r * 64 + k] * w;
        }
#pragma unroll
        for (int r = 0; r < SROWS; r++)
            sens[(size_t)(row0 + r) * DZ + tid] = acc[r];
    }
}

// ---------------- EnKF per batch element ----------------
__global__ void __launch_bounds__(256)
enkf_kernel(const float* __restrict__ part, const float* __restrict__ pm_bm2,
            const float* __restrict__ sens,
            const float* __restrict__ on_w1, const float* __restrict__ on_b1,
            const float* __restrict__ on_w2, const float* __restrict__ on_b2,
            float* __restrict__ out1, float* __restrict__ out2,
            float* __restrict__ out3, float* __restrict__ out4,
            float* __restrict__ out5)
{
    const int b = blockIdx.x, tid = threadIdx.x;
    __shared__ float pred[ENS][DX], ez[ENS][DZ], Am[ENS][DX], corr[ENS][DX];
    __shared__ float sm[DX], zm[DZ], rdiag[DZ], hid[32];
    __shared__ float Mm[DX][DX], Km[DX][DZ], aug[DX][2 * DX], fac[DX];

    for (int i = tid; i < ENS * DX; i += 256) {
        int e = i / DX, j = i % DX;
        size_t row = (size_t)b * ENS + e;
        float p = pm_bm2[j];
#pragma unroll
        for (int q = 0; q < 8; q++) p += part[((size_t)q * BE + row) * DX + j];
        pred[e][j] = p;
    }
    for (int i = tid; i < ENS * DZ; i += 256) {
        int e = i / DZ, j = i % DZ;
        int src = (b * ENS + e) % BATCH;
        float v = sens[src * DZ + j];
        ez[e][j] = v;
        out5[(size_t)(b * ENS + e) * DZ + j] = v;
    }
    __syncthreads();
    if (tid < DX) {
        float s1 = 0.f, s2 = 0.f;
        for (int e = 0; e < ENS; e++) { s1 += pred[e][tid]; s2 += ez[e][tid]; }
        float m1 = s1 * (1.f / ENS), m2 = s2 * (1.f / ENS);
        sm[tid] = m1; zm[tid] = m2;
        out3[b * DX + tid] = m1;
        out4[b * DZ + tid] = m2;
    }
    __syncthreads();
    if (tid < 32) {
        float a = on_b1[tid];
        for (int i = 0; i < DZ; i++) a += zm[i] * on_w1[i * 32 + tid];
        hid[tid] = a > 0.f ? a : 0.f;
    }
    __syncthreads();
    if (tid < DZ) {
        float a = on_b2[tid];
        for (int j = 0; j < 32; j++) a += hid[j] * on_w2[j * DZ + tid];
        a += 0.001f;
        rdiag[tid] = a * a + 0.038729833f;
    }
    for (int i = tid; i < ENS * DX; i += 256)
        Am[i / DX][i % DX] = pred[i / DX][i % DX] - sm[i % DX];
    __syncthreads();
    if (tid < DX * DX) {
        int i = tid / DX, j = tid % DX;
        float s = 0.f;
        for (int e = 0; e < ENS; e++) s += Am[e][i] * Am[e][j];
        float m = s * (1.f / (ENS - 1));
        Mm[i][j] = m;
        aug[i][j] = m + (i == j ? rdiag[i] : 0.f);
        aug[i][DX + j] = (i == j) ? 1.f : 0.f;
    }
    __syncthreads();
    for (int p = 0; p < DX; p++) {
        float pv = aug[p][p];
        __syncthreads();
        if (tid < 2 * DX) aug[p][tid] *= (1.f / pv);
        if (tid < DX) fac[tid] = (tid == p) ? 0.f : aug[tid][p];
        __syncthreads();
        for (int t = tid; t < DX * 2 * DX; t += 256) {
            int rr = t / (2 * DX), c = t % (2 * DX);
            if (rr != p) aug[rr][c] -= fac[rr] * aug[p][c];
        }
        __syncthreads();
    }
    if (tid < DX * DX) {
        int i = tid / DX, j = tid % DX;
        float s = 0.f;
        for (int k = 0; k < DX; k++) s += Mm[i][k] * aug[k][DX + j];
        Km[i][j] = s;
    }
    __syncthreads();
    for (int t = tid; t < ENS * DX; t += 256) {
        int e = t / DX, i = t % DX;
        float s = pred[e][i];
        for (int j = 0; j < DZ; j++) s += Km[i][j] * (ez[e][j] - pred[e][j]);
        corr[e][i] = s;
        out1[(size_t)(b * ENS + e) * DX + i] = s;
    }
    __syncthreads();
    if (tid < DX) {
        float s = 0.f;
        for (int e = 0; e < ENS; e++) s += corr[e][tid];
        out2[b * DX + tid] = s * (1.f / ENS);
    }
}

// ---------------- launcher ----------------
extern "C" void kernel_launch(void* const* d_in, const int* in_sizes, int n_in,
                              void* d_out, int out_size)
{
    const float* raw    = (const float*)d_in[0];
    const float* sp     = (const float*)d_in[1];
    const float* pm_w1  = (const float*)d_in[2];
    const float* pm_b1  = (const float*)d_in[3];
    const float* pm_w3  = (const float*)d_in[4];
    const float* pm_b3  = (const float*)d_in[5];
    const float* pm_wm2 = (const float*)d_in[6];
    const float* pm_bm2 = (const float*)d_in[7];
    const float* sm_w2  = (const float*)d_in[8];
    const float* sm_b2  = (const float*)d_in[9];
    const float* sm_w3  = (const float*)d_in[10];
    const float* sm_b3  = (const float*)d_in[11];
    const float* sm_w5  = (const float*)d_in[12];
    const float* sm_b5  = (const float*)d_in[13];
    const float* sm_w6  = (const float*)d_in[14];
    const float* sm_b6  = (const float*)d_in[15];
    const float* on_w1  = (const float*)d_in[16];
    const float* on_b1  = (const float*)d_in[17];
    const float* on_w2  = (const float*)d_in[18];
    const float* on_b2  = (const float*)d_in[19];

    float* out = (float*)d_out;

    uint32_t *xp, *w1p, *w3p, *h1p;
    float *partp, *sensp;
    cudaGetSymbolAddress((void**)&xp,  g_x);
    cudaGetSymbolAddress((void**)&w1p, g_w1);
    cudaGetSymbolAddress((void**)&w3p, g_w3);
    cudaGetSymbolAddress((void**)&h1p, g_h1);
    cudaGetSymbolAddress((void**)&partp, g_part);
    cudaGetSymbolAddress((void**)&sensp, g_sens);

    cudaFuncSetAttribute(gemm_hmma<3, 0>, cudaFuncAttributeMaxDynamicSharedMemorySize, DYN_SMEM);
    cudaFuncSetAttribute(gemm_hmma<4, 1>, cudaFuncAttributeMaxDynamicSharedMemorySize, DYN_SMEM);

    prep_w_kernel<<<(256 * 96 + 512 * 128 + 255) / 256, 256>>>(pm_w1, pm_w3);
    prep_x_kernel<<<BE * 96 / 256, 256>>>(sp);

    // GEMM A: h1 = leaky(x @ w1 + b1)  [BE x 256], K=192 (padded)
    gemm_hmma<3, 0><<<dim3(2, BE / 128), 256, DYN_SMEM>>>(xp, w1p, 96, pm_b1, nullptr);
    // GEMM B: fused leaky(h1 @ w3 + b3) @ wm2 -> partials, K=256
    gemm_hmma<4, 1><<<dim3(4, BE / 128), 256, DYN_SMEM>>>(h1p, w3p, 128, pm_b3, pm_wm2);

    sensor_kernel<<<BATCH / SROWS, 256>>>(raw, sm_w2, sm_b2, sm_w3, sm_b3,
                                          sm_w5, sm_b5, sm_w6, sm_b6, sensp);
    enkf_kernel<<<BATCH, 256>>>(partp, pm_bm2, sensp, on_w1, on_b1, on_w2, on_b2,
                                out + O1_OFF, out + O2_OFF, out + O3_OFF,
                                out + O4_OFF, out + O5_OFF);
}

// round 15
// speedup vs baseline: 1.4016x; 1.1107x over previous
#include <cuda_runtime.h>
#include <cuda_fp16.h>
#include <cstdint>

#define BATCH 2048
#define ENS   32
#define DX    14
#define DZ    14
#define PM_IN 140
#define SM_IN 220
#define BE    (BATCH * ENS)

#define O1_OFF 0
#define O2_OFF (BATCH * ENS * DX)
#define O3_OFF (O2_OFF + BATCH * DX)
#define O4_OFF (O3_OFF + BATCH * DX)
#define O5_OFF (O4_OFF + BATCH * DZ)

// smem layout (per CTA): 3 stages x 32KB tiles, then bias, then wm2 slice
#define STAGE_BYTES 32768
#define BIAS_OFF    98304
#define WM2_OFF     98816
#define DYN_SMEM    107008

// ---------------- scratch globals (uint32 = packed fp16 pair) ----------------
__device__ uint32_t g_x [(size_t)BE * 96];     // x   fp16 [BE][192]
__device__ uint32_t g_w1[256 * 96];            // w1^T fp16 [256][192]
__device__ uint32_t g_w3[512 * 128];           // w3^T fp16 [512][256]
__device__ uint32_t g_h1[(size_t)BE * 128];    // h1  fp16 [BE][256]
__device__ float    g_part[(size_t)8 * BE * DX];   // 8 partial slices
__device__ float    g_sens[BATCH * DZ];

// ---------------- helpers ----------------
__device__ __forceinline__ uint32_t smem_u32(const void* p) {
    uint32_t a;
    asm("{ .reg .u64 t; cvta.to.shared.u64 t, %1; cvt.u32.u64 %0, t; }" : "=r"(a) : "l"(p));
    return a;
}
#define CP16(d, s) asm volatile("cp.async.cg.shared.global [%0], [%1], 16;" :: "r"(d), "l"(s))
#define CP_COMMIT() asm volatile("cp.async.commit_group;")
#define CP_WAITG(n) asm volatile("cp.async.wait_group %0;" :: "n"(n) : "memory")

__device__ __forceinline__ void ldsm4(uint32_t (&r)[4], uint32_t addr) {
    asm volatile("ldmatrix.sync.aligned.m8n8.x4.shared.b16 {%0,%1,%2,%3}, [%4];"
                 : "=r"(r[0]), "=r"(r[1]), "=r"(r[2]), "=r"(r[3]) : "r"(addr));
}
__device__ __forceinline__ void mma_f16(float (&d)[4], const uint32_t (&a)[4],
                                        uint32_t b0, uint32_t b1) {
    asm volatile(
        "mma.sync.aligned.m16n8k16.row.col.f32.f16.f16.f32 "
        "{%0,%1,%2,%3}, {%4,%5,%6,%7}, {%8,%9}, {%0,%1,%2,%3};"
        : "+f"(d[0]), "+f"(d[1]), "+f"(d[2]), "+f"(d[3])
        : "r"(a[0]), "r"(a[1]), "r"(a[2]), "r"(a[3]), "r"(b0), "r"(b1));
}
__device__ __forceinline__ uint32_t packA2(float v0, float v1) {
    __half h0 = __float2half_rn(v0), h1 = __float2half_rn(v1);
    return (uint32_t)__half_as_ushort(h0) | ((uint32_t)__half_as_ushort(h1) << 16);
}

// ---------------- prep: x -> fp16, K padded to 192 ----------------
__global__ void __launch_bounds__(256)
prep_x_kernel(const float* __restrict__ x)
{
    int idx = blockIdx.x * 256 + threadIdx.x;   // BE*96
    int row = idx / 96, p = idx % 96, k = 2 * p;
    float v0 = (k < PM_IN) ? x[(size_t)row * PM_IN + k] : 0.f;
    float v1 = (k + 1 < PM_IN) ? x[(size_t)row * PM_IN + k + 1] : 0.f;
    g_x[(size_t)row * 96 + p] = packA2(v0, v1);
}

// ---------------- prep: weights transposed -> fp16 ----------------
__global__ void __launch_bounds__(256)
prep_w_kernel(const float* __restrict__ w1, const float* __restrict__ w3)
{
    int idx = blockIdx.x * 256 + threadIdx.x;
    if (idx < 256 * 96) {                        // w1 [140][256] -> [256][192]
        int n = idx / 96, p = idx % 96, k = 2 * p;
        float v0 = (k < PM_IN) ? w1[(size_t)k * 256 + n] : 0.f;
        float v1 = (k + 1 < PM_IN) ? w1[(size_t)(k + 1) * 256 + n] : 0.f;
        g_w1[idx] = packA2(v0, v1);
    } else if (idx < 256 * 96 + 512 * 128) {     // w3 [256][512] -> [512][256]
        int i2 = idx - 256 * 96;
        int n = i2 / 128, p = i2 % 128, k = 2 * p;
        g_w3[i2] = packA2(w3[(size_t)k * 512 + n], w3[(size_t)(k + 1) * 512 + n]);
    }
}

// ---------------- HMMA fp16 GEMM: 8 warps, 2 CTAs/SM, 3-stage pipeline -----
// CTA tile 128x128, BK=64, 8 warps (4m x 2n), warp tile 32x64.  (R10 proven)
template <int KCHUNKS, int EPI>
__global__ void __launch_bounds__(256, 2)
gemm_hmma(const uint32_t* __restrict__ A, const uint32_t* __restrict__ B,
          int kstr, const float* __restrict__ bias, const float* __restrict__ wm2)
{
    extern __shared__ char smem[];
    const uint32_t ub = smem_u32(smem);
    float* biasS = (float*)(smem + BIAS_OFF);
    float* wm2s  = (float*)(smem + WM2_OFF);

    const int tid = threadIdx.x, wid = tid >> 5, lane = tid & 31;
    const int bn = blockIdx.x, bt = blockIdx.y;
    const int mw = (wid >> 1) * 32;
    const int nw = (wid & 1) * 64;

    if (tid < 128) biasS[tid] = bias[bn * 128 + tid];
    if (EPI == 1) {
        for (int i = tid; i < 128 * DX; i += 256) {
            int c = i / DX, m = i % DX;
            wm2s[c * 16 + m] = wm2[(size_t)(bn * 128 + c) * DX + m];
        }
    }

    auto issue_load = [&](int stage, int kc) {
        const uint32_t sb = ub + stage * STAGE_BYTES;
#pragma unroll
        for (int q = 0; q < 8; q++) {
            int i = tid + 256 * q;
            int t = i >> 10, r = (i >> 3) & 127, c = i & 7;
            const uint32_t* gp = t ? B : A;
            int grow = (t ? bn : bt) * 128 + r;
            const uint32_t* src = gp + (size_t)grow * kstr + kc * 32 + c * 4;
            uint32_t dst = sb + t * 16384 + r * 128 + ((c * 16) ^ ((r & 7) << 4));
            CP16(dst, src);
        }
        CP_COMMIT();
    };

    float acc[2][8][4];
#pragma unroll
    for (int f = 0; f < 2; f++)
#pragma unroll
        for (int g = 0; g < 8; g++)
#pragma unroll
            for (int e = 0; e < 4; e++) acc[f][g][e] = 0.f;

    issue_load(0, 0);
    if (KCHUNKS > 1) issue_load(1, 1);

#pragma unroll 1
    for (int kc = 0; kc < KCHUNKS; kc++) {
        if (kc + 2 < KCHUNKS) {
            issue_load((kc + 2) % 3, kc + 2);
            CP_WAITG(2);
        } else if (kc + 1 < KCHUNKS) {
            CP_WAITG(1);
        } else {
            CP_WAITG(0);
        }
        __syncthreads();

        const uint32_t sb = ub + (kc % 3) * STAGE_BYTES;
#pragma unroll
        for (int k16 = 0; k16 < 4; k16++) {
            uint32_t ah[2][4];
#pragma unroll
            for (int f = 0; f < 2; f++) {
                int mrow = mw + f * 16 + (lane & 15);
                int cb = k16 * 32 + ((lane >> 4) << 4);
                uint32_t off = mrow * 128 + (cb ^ ((mrow & 7) << 4));
                ldsm4(ah[f], sb + off);
            }
            uint32_t bh[4][4];
#pragma unroll
            for (int g = 0; g < 4; g++) {
                int nrow = nw + g * 16 + ((lane >> 4) << 3) + (lane & 7);
                int cb = k16 * 32 + (((lane >> 3) & 1) << 4);
                uint32_t off = nrow * 128 + (cb ^ ((nrow & 7) << 4));
                ldsm4(bh[g], sb + 16384 + off);
            }
#pragma unroll
            for (int f = 0; f < 2; f++)
#pragma unroll
                for (int g = 0; g < 4; g++) {
                    mma_f16(acc[f][2 * g],     ah[f], bh[g][0], bh[g][1]);
                    mma_f16(acc[f][2 * g + 1], ah[f], bh[g][2], bh[g][3]);
                }
        }
        __syncthreads();
    }

    if (EPI == 0) {
#pragma unroll
        for (int f = 0; f < 2; f++) {
            int row0 = bt * 128 + mw + f * 16 + (lane >> 2);
#pragma unroll
            for (int nf = 0; nf < 8; nf++) {
                int col = nw + nf * 8 + 2 * (lane & 3);
                float b0 = biasS[col], b1 = biasS[col + 1];
                float v0 = acc[f][nf][0] + b0, v1 = acc[f][nf][1] + b1;
                float v2 = acc[f][nf][2] + b0, v3 = acc[f][nf][3] + b1;
                v0 = v0 >= 0.f ? v0 : 0.01f * v0;
                v1 = v1 >= 0.f ? v1 : 0.01f * v1;
                v2 = v2 >= 0.f ? v2 : 0.01f * v2;
                v3 = v3 >= 0.f ? v3 : 0.01f * v3;
                int gcol = bn * 128 + col;
                g_h1[(size_t)row0 * 128 + gcol / 2]       = packA2(v0, v1);
                g_h1[(size_t)(row0 + 8) * 128 + gcol / 2] = packA2(v2, v3);
            }
        }
    } else {
        float proj[4][DX];
#pragma unroll
        for (int s2 = 0; s2 < 4; s2++)
#pragma unroll
            for (int m = 0; m < DX; m++) proj[s2][m] = 0.f;
#pragma unroll
        for (int f = 0; f < 2; f++)
#pragma unroll
            for (int nf = 0; nf < 8; nf++) {
                int col = nw + nf * 8 + 2 * (lane & 3);
#pragma unroll
                for (int e = 0; e < 2; e++) {
                    int c = col + e;
                    float b = biasS[c];
                    float v0 = acc[f][nf][e] + b;
                    float v1 = acc[f][nf][2 + e] + b;
                    v0 = v0 >= 0.f ? v0 : 0.01f * v0;
                    v1 = v1 >= 0.f ? v1 : 0.01f * v1;
                    const float* wr = wm2s + c * 16;
#pragma unroll
                    for (int m = 0; m < DX; m++) {
                        float wv = wr[m];
                        proj[2 * f][m]     += v0 * wv;
                        proj[2 * f + 1][m] += v1 * wv;
                    }
                }
            }
#pragma unroll
        for (int s2 = 0; s2 < 4; s2++)
#pragma unroll
            for (int m = 0; m < DX; m++) {
                proj[s2][m] += __shfl_xor_sync(0xFFFFFFFFu, proj[s2][m], 1);
                proj[s2][m] += __shfl_xor_sync(0xFFFFFFFFu, proj[s2][m], 2);
            }
        if ((lane & 3) == 0) {
            int slice = bn * 2 + (wid & 1);
#pragma unroll
            for (int s2 = 0; s2 < 4; s2++) {
                int row = bt * 128 + mw + (s2 >> 1) * 16 + (lane >> 2) + (s2 & 1) * 8;
                float* dst = g_part + ((size_t)slice * BE + row) * DX;
#pragma unroll
                for (int m = 0; m < DX; m++) dst[m] = proj[s2][m];
            }
        }
    }
}

// ---------------- sensor MLP: 8 rows/block (grid 256), full-thread tails ---
#define SROWS 8
__global__ void __launch_bounds__(256)
sensor_kernel(const float* __restrict__ raw,
              const float* __restrict__ w2, const float* __restrict__ b2,
              const float* __restrict__ w3, const float* __restrict__ b3,
              const float* __restrict__ w5, const float* __restrict__ b5,
              const float* __restrict__ w6, const float* __restrict__ b6,
              float* __restrict__ sens)
{
    __shared__ float bufA[SROWS * 256];   // layer1 input (stride 220), later h2 (stride 256)
    __shared__ float h1s [SROWS * 256];
    __shared__ float h3s [SROWS * 64];
    const int tid = threadIdx.x;
    const int row0 = blockIdx.x * SROWS;

    for (int i = tid; i < SROWS * SM_IN; i += 256) {
        int r = i / SM_IN, k = i % SM_IN;
        bufA[r * SM_IN + k] = raw[(size_t)(row0 + r) * SM_IN + k];
    }
    __syncthreads();

    float acc[SROWS];
    {   // layer 1: 220 -> 256, leaky
#pragma unroll
        for (int r = 0; r < SROWS; r++) acc[r] = b2[tid];
#pragma unroll 4
        for (int k = 0; k < SM_IN; k++) {
            float w = w2[k * 256 + tid];
#pragma unroll
            for (int r = 0; r < SROWS; r++) acc[r] += bufA[r * SM_IN + k] * w;
        }
#pragma unroll
        for (int r = 0; r < SROWS; r++)
            h1s[r * 256 + tid] = acc[r] >= 0.f ? acc[r] : 0.01f * acc[r];
    }
    __syncthreads();
    {   // layer 2: 256 -> 256, leaky (output into bufA, stride 256)
#pragma unroll
        for (int r = 0; r < SROWS; r++) acc[r] = b3[tid];
#pragma unroll 4
        for (int k = 0; k < 256; k++) {
            float w = w3[k * 256 + tid];
#pragma unroll
            for (int r = 0; r < SROWS; r++) acc[r] += h1s[r * 256 + k] * w;
        }
        __syncthreads();
#pragma unroll
        for (int r = 0; r < SROWS; r++)
            bufA[r * 256 + tid] = acc[r] >= 0.f ? acc[r] : 0.01f * acc[r];
    }
    __syncthreads();
    {   // layer 3: 256 -> 64, leaky. 256 threads = 64 cols x 4 row-groups (2 rows each)
        int col = tid & 63, rg = tid >> 6;
        float a0 = b5[col], a1 = a0;
        int r0 = rg * 2, r1 = rg * 2 + 1;
#pragma unroll 4
        for (int k = 0; k < 256; k++) {
            float w = w5[k * 64 + col];
            a0 += bufA[r0 * 256 + k] * w;
            a1 += bufA[r1 * 256 + k] * w;
        }
        h3s[r0 * 64 + col] = a0 >= 0.f ? a0 : 0.01f * a0;
        h3s[r1 * 64 + col] = a1 >= 0.f ? a1 : 0.01f * a1;
    }
    __syncthreads();
    if (tid < SROWS * DZ) {   // layer 4: 64 -> 14, linear. 112 threads = 14 cols x 8 rows
        int col = tid % DZ, r = tid / DZ;
        float a = b6[col];
#pragma unroll 4
        for (int k = 0; k < 64; k++)
            a += h3s[r * 64 + k] * w6[k * DZ + col];
        sens[(size_t)(row0 + r) * DZ + col] = a;
    }
}

// ---------------- EnKF per batch element ----------------
__global__ void __launch_bounds__(256)
enkf_kernel(const float* __restrict__ part, const float* __restrict__ pm_bm2,
            const float* __restrict__ sens,
            const float* __restrict__ on_w1, const float* __restrict__ on_b1,
            const float* __restrict__ on_w2, const float* __restrict__ on_b2,
            float* __restrict__ out1, float* __restrict__ out2,
            float* __restrict__ out3, float* __restrict__ out4,
            float* __restrict__ out5)
{
    const int b = blockIdx.x, tid = threadIdx.x;
    __shared__ float pred[ENS][DX], ez[ENS][DZ], Am[ENS][DX], corr[ENS][DX];
    __shared__ float sm[DX], zm[DZ], rdiag[DZ], hid[32];
    __shared__ float Mm[DX][DX], Km[DX][DZ], aug[DX][2 * DX], fac[DX];

    for (int i = tid; i < ENS * DX; i += 256) {
        int e = i / DX, j = i % DX;
        size_t row = (size_t)b * ENS + e;
        float p = pm_bm2[j];
#pragma unroll
        for (int q = 0; q < 8; q++) p += part[((size_t)q * BE + row) * DX + j];
        pred[e][j] = p;
    }
    for (int i = tid; i < ENS * DZ; i += 256) {
        int e = i / DZ, j = i % DZ;
        int src = (b * ENS + e) % BATCH;
        float v = sens[src * DZ + j];
        ez[e][j] = v;
        out5[(size_t)(b * ENS + e) * DZ + j] = v;
    }
    __syncthreads();
    if (tid < DX) {
        float s1 = 0.f, s2 = 0.f;
        for (int e = 0; e < ENS; e++) { s1 += pred[e][tid]; s2 += ez[e][tid]; }
        float m1 = s1 * (1.f / ENS), m2 = s2 * (1.f / ENS);
        sm[tid] = m1; zm[tid] = m2;
        out3[b * DX + tid] = m1;
        out4[b * DZ + tid] = m2;
    }
    __syncthreads();
    if (tid < 32) {
        float a = on_b1[tid];
        for (int i = 0; i < DZ; i++) a += zm[i] * on_w1[i * 32 + tid];
        hid[tid] = a > 0.f ? a : 0.f;
    }
    __syncthreads();
    if (tid < DZ) {
        float a = on_b2[tid];
        for (int j = 0; j < 32; j++) a += hid[j] * on_w2[j * DZ + tid];
        a += 0.001f;
        rdiag[tid] = a * a + 0.038729833f;
    }
    for (int i = tid; i < ENS * DX; i += 256)
        Am[i / DX][i % DX] = pred[i / DX][i % DX] - sm[i % DX];
    __syncthreads();
    if (tid < DX * DX) {
        int i = tid / DX, j = tid % DX;
        float s = 0.f;
        for (int e = 0; e < ENS; e++) s += Am[e][i] * Am[e][j];
        float m = s * (1.f / (ENS - 1));
        Mm[i][j] = m;
        aug[i][j] = m + (i == j ? rdiag[i] : 0.f);
        aug[i][DX + j] = (i == j) ? 1.f : 0.f;
    }
    __syncthreads();
    for (int p = 0; p < DX; p++) {
        float pv = aug[p][p];
        __syncthreads();
        if (tid < 2 * DX) aug[p][tid] *= (1.f / pv);
        if (tid < DX) fac[tid] = (tid == p) ? 0.f : aug[tid][p];
        __syncthreads();
        for (int t = tid; t < DX * 2 * DX; t += 256) {
            int rr = t / (2 * DX), c = t % (2 * DX);
            if (rr != p) aug[rr][c] -= fac[rr] * aug[p][c];
        }
        __syncthreads();
    }
    if (tid < DX * DX) {
        int i = tid / DX, j = tid % DX;
        float s = 0.f;
        for (int k = 0; k < DX; k++) s += Mm[i][k] * aug[k][DX + j];
        Km[i][j] = s;
    }
    __syncthreads();
    for (int t = tid; t < ENS * DX; t += 256) {
        int e = t / DX, i = t % DX;
        float s = pred[e][i];
        for (int j = 0; j < DZ; j++) s += Km[i][j] * (ez[e][j] - pred[e][j]);
        corr[e][i] = s;
        out1[(size_t)(b * ENS + e) * DX + i] = s;
    }
    __syncthreads();
    if (tid < DX) {
        float s = 0.f;
        for (int e = 0; e < ENS; e++) s += corr[e][tid];
        out2[b * DX + tid] = s * (1.f / ENS);
    }
}

// ---------------- launcher ----------------
extern "C" void kernel_launch(void* const* d_in, const int* in_sizes, int n_in,
                              void* d_out, int out_size)
{
    const float* raw    = (const float*)d_in[0];
    const float* sp     = (const float*)d_in[1];
    const float* pm_w1  = (const float*)d_in[2];
    const float* pm_b1  = (const float*)d_in[3];
    const float* pm_w3  = (const float*)d_in[4];
    const float* pm_b3  = (const float*)d_in[5];
    const float* pm_wm2 = (const float*)d_in[6];
    const float* pm_bm2 = (const float*)d_in[7];
    const float* sm_w2  = (const float*)d_in[8];
    const float* sm_b2  = (const float*)d_in[9];
    const float* sm_w3  = (const float*)d_in[10];
    const float* sm_b3  = (const float*)d_in[11];
    const float* sm_w5  = (const float*)d_in[12];
    const float* sm_b5  = (const float*)d_in[13];
    const float* sm_w6  = (const float*)d_in[14];
    const float* sm_b6  = (const float*)d_in[15];
    const float* on_w1  = (const float*)d_in[16];
    const float* on_b1  = (const float*)d_in[17];
    const float* on_w2  = (const float*)d_in[18];
    const float* on_b2  = (const float*)d_in[19];

    float* out = (float*)d_out;

    uint32_t *xp, *w1p, *w3p, *h1p;
    float *partp, *sensp;
    cudaGetSymbolAddress((void**)&xp,  g_x);
    cudaGetSymbolAddress((void**)&w1p, g_w1);
    cudaGetSymbolAddress((void**)&w3p, g_w3);
    cudaGetSymbolAddress((void**)&h1p, g_h1);
    cudaGetSymbolAddress((void**)&partp, g_part);
    cudaGetSymbolAddress((void**)&sensp, g_sens);

    cudaFuncSetAttribute(gemm_hmma<3, 0>, cudaFuncAttributeMaxDynamicSharedMemorySize, DYN_SMEM);
    cudaFuncSetAttribute(gemm_hmma<4, 1>, cudaFuncAttributeMaxDynamicSharedMemorySize, DYN_SMEM);

    prep_w_kernel<<<(256 * 96 + 512 * 128 + 255) / 256, 256>>>(pm_w1, pm_w3);
    prep_x_kernel<<<BE * 96 / 256, 256>>>(sp);

    // GEMM A: h1 = leaky(x @ w1 + b1)  [BE x 256], K=192 (padded)
    gemm_hmma<3, 0><<<dim3(2, BE / 128), 256, DYN_SMEM>>>(xp, w1p, 96, pm_b1, nullptr);
    // GEMM B: fused leaky(h1 @ w3 + b3) @ wm2 -> partials, K=256
    gemm_hmma<4, 1><<<dim3(4, BE / 128), 256, DYN_SMEM>>>(h1p, w3p, 128, pm_b3, pm_wm2);

    sensor_kernel<<<BATCH / SROWS, 256>>>(raw, sm_w2, sm_b2, sm_w3, sm_b3,
                                          sm_w5, sm_b5, sm_w6, sm_b6, sensp);
    enkf_kernel<<<BATCH, 256>>>(partp, pm_bm2, sensp, on_w1, on_b1, on_w2, on_b2,
                                out + O1_OFF, out + O2_OFF, out + O3_OFF,
                                out + O4_OFF, out + O5_OFF);
}

// round 16
// speedup vs baseline: 1.4857x; 1.0600x over previous
#include <cuda_runtime.h>
#include <cuda_fp16.h>
#include <cstdint>

#define BATCH 2048
#define ENS   32
#define DX    14
#define DZ    14
#define PM_IN 140
#define SM_IN 220
#define BE    (BATCH * ENS)

#define O1_OFF 0
#define O2_OFF (BATCH * ENS * DX)
#define O3_OFF (O2_OFF + BATCH * DX)
#define O4_OFF (O3_OFF + BATCH * DX)
#define O5_OFF (O4_OFF + BATCH * DZ)

// smem layout (per CTA): 3 stages x 32KB tiles, then bias, then wm2 slice
#define STAGE_BYTES 32768
#define BIAS_OFF    98304
#define WM2_OFF     98816
#define DYN_SMEM    107008

// ---------------- scratch globals (uint32 = packed fp16 pair) ----------------
__device__ uint32_t g_x [(size_t)BE * 96];     // x   fp16 [BE][192]
__device__ uint32_t g_w1[256 * 96];            // w1^T fp16 [256][192]
__device__ uint32_t g_w3[512 * 128];           // w3^T fp16 [512][256]
__device__ uint32_t g_h1[(size_t)BE * 128];    // h1  fp16 [BE][256]
__device__ float    g_part[(size_t)8 * BE * DX];   // 8 partial slices
__device__ float    g_sens[BATCH * DZ];

// ---------------- helpers ----------------
__device__ __forceinline__ uint32_t smem_u32(const void* p) {
    uint32_t a;
    asm("{ .reg .u64 t; cvta.to.shared.u64 t, %1; cvt.u32.u64 %0, t; }" : "=r"(a) : "l"(p));
    return a;
}
#define CP16(d, s) asm volatile("cp.async.cg.shared.global [%0], [%1], 16;" :: "r"(d), "l"(s))
#define CP_COMMIT() asm volatile("cp.async.commit_group;")
#define CP_WAITG(n) asm volatile("cp.async.wait_group %0;" :: "n"(n) : "memory")

__device__ __forceinline__ void ldsm4(uint32_t (&r)[4], uint32_t addr) {
    asm volatile("ldmatrix.sync.aligned.m8n8.x4.shared.b16 {%0,%1,%2,%3}, [%4];"
                 : "=r"(r[0]), "=r"(r[1]), "=r"(r[2]), "=r"(r[3]) : "r"(addr));
}
__device__ __forceinline__ void mma_f16(float (&d)[4], const uint32_t (&a)[4],
                                        uint32_t b0, uint32_t b1) {
    asm volatile(
        "mma.sync.aligned.m16n8k16.row.col.f32.f16.f16.f32 "
        "{%0,%1,%2,%3}, {%4,%5,%6,%7}, {%8,%9}, {%0,%1,%2,%3};"
        : "+f"(d[0]), "+f"(d[1]), "+f"(d[2]), "+f"(d[3])
        : "r"(a[0]), "r"(a[1]), "r"(a[2]), "r"(a[3]), "r"(b0), "r"(b1));
}
__device__ __forceinline__ uint32_t packA2(float v0, float v1) {
    __half h0 = __float2half_rn(v0), h1 = __float2half_rn(v1);
    return (uint32_t)__half_as_ushort(h0) | ((uint32_t)__half_as_ushort(h1) << 16);
}

// ---------------- prep: x -> fp16, K padded to 192 ----------------
__global__ void __launch_bounds__(256)
prep_x_kernel(const float* __restrict__ x)
{
    int idx = blockIdx.x * 256 + threadIdx.x;   // BE*96
    int row = idx / 96, p = idx % 96, k = 2 * p;
    float v0 = (k < PM_IN) ? x[(size_t)row * PM_IN + k] : 0.f;
    float v1 = (k + 1 < PM_IN) ? x[(size_t)row * PM_IN + k + 1] : 0.f;
    g_x[(size_t)row * 96 + p] = packA2(v0, v1);
}

// ---------------- prep: weights transposed -> fp16 ----------------
__global__ void __launch_bounds__(256)
prep_w_kernel(const float* __restrict__ w1, const float* __restrict__ w3)
{
    int idx = blockIdx.x * 256 + threadIdx.x;
    if (idx < 256 * 96) {                        // w1 [140][256] -> [256][192]
        int n = idx / 96, p = idx % 96, k = 2 * p;
        float v0 = (k < PM_IN) ? w1[(size_t)k * 256 + n] : 0.f;
        float v1 = (k + 1 < PM_IN) ? w1[(size_t)(k + 1) * 256 + n] : 0.f;
        g_w1[idx] = packA2(v0, v1);
    } else if (idx < 256 * 96 + 512 * 128) {     // w3 [256][512] -> [512][256]
        int i2 = idx - 256 * 96;
        int n = i2 / 128, p = i2 % 128, k = 2 * p;
        g_w3[i2] = packA2(w3[(size_t)k * 512 + n], w3[(size_t)(k + 1) * 512 + n]);
    }
}

// ---------------- sensor MLP as a device block (8 rows/block) -------------
__device__ void sensor_block(char* smem, int sblk,
                             const float* __restrict__ raw,
                             const float* __restrict__ w2, const float* __restrict__ b2,
                             const float* __restrict__ w3, const float* __restrict__ b3,
                             const float* __restrict__ w5, const float* __restrict__ b5,
                             const float* __restrict__ w6, const float* __restrict__ b6,
                             float* __restrict__ sens)
{
    float* bufA = (float*)smem;              // 8*256 floats (input stride 220, then h2 stride 256)
    float* h1s  = (float*)(smem + 8192);     // 8*256
    float* h3s  = (float*)(smem + 16384);    // 8*64
    const int tid = threadIdx.x;
    const int row0 = sblk * 8;

    for (int i = tid; i < 8 * SM_IN; i += 256) {
        int r = i / SM_IN, k = i % SM_IN;
        bufA[r * SM_IN + k] = raw[(size_t)(row0 + r) * SM_IN + k];
    }
    __syncthreads();

    float acc[8];
    {   // layer 1: 220 -> 256, leaky
#pragma unroll
        for (int r = 0; r < 8; r++) acc[r] = b2[tid];
#pragma unroll 4
        for (int k = 0; k < SM_IN; k++) {
            float w = w2[k * 256 + tid];
#pragma unroll
            for (int r = 0; r < 8; r++) acc[r] += bufA[r * SM_IN + k] * w;
        }
#pragma unroll
        for (int r = 0; r < 8; r++)
            h1s[r * 256 + tid] = acc[r] >= 0.f ? acc[r] : 0.01f * acc[r];
    }
    __syncthreads();
    {   // layer 2: 256 -> 256, leaky -> bufA (stride 256)
#pragma unroll
        for (int r = 0; r < 8; r++) acc[r] = b3[tid];
#pragma unroll 4
        for (int k = 0; k < 256; k++) {
            float w = w3[k * 256 + tid];
#pragma unroll
            for (int r = 0; r < 8; r++) acc[r] += h1s[r * 256 + k] * w;
        }
        __syncthreads();
#pragma unroll
        for (int r = 0; r < 8; r++)
            bufA[r * 256 + tid] = acc[r] >= 0.f ? acc[r] : 0.01f * acc[r];
    }
    __syncthreads();
    {   // layer 3: 256 -> 64, leaky. 256 thr = 64 cols x 4 row-groups x 2 rows
        int col = tid & 63, rg = tid >> 6;
        float a0 = b5[col], a1 = a0;
        int r0 = rg * 2, r1 = rg * 2 + 1;
#pragma unroll 4
        for (int k = 0; k < 256; k++) {
            float w = w5[k * 64 + col];
            a0 += bufA[r0 * 256 + k] * w;
            a1 += bufA[r1 * 256 + k] * w;
        }
        h3s[r0 * 64 + col] = a0 >= 0.f ? a0 : 0.01f * a0;
        h3s[r1 * 64 + col] = a1 >= 0.f ? a1 : 0.01f * a1;
    }
    __syncthreads();
    if (tid < 8 * DZ) {   // layer 4: 64 -> 14, linear. 112 thr = 14 cols x 8 rows
        int col = tid % DZ, r = tid / DZ;
        float a = b6[col];
#pragma unroll 4
        for (int k = 0; k < 64; k++)
            a += h3s[r * 64 + k] * w6[k * DZ + col];
        sens[(size_t)(row0 + r) * DZ + col] = a;
    }
}

// ---------------- HMMA fp16 GEMM: 8 warps, 2 CTAs/SM, 3-stage pipeline -----
// CTA tile 128x128, BK=64, 8 warps (4m x 2n), warp tile 32x64.  (R10 proven)
// SENSOR=1 (EPI=1): blocks with blockIdx.y >= 512 run the sensor MLP instead.
template <int KCHUNKS, int EPI, int SENSOR>
__global__ void __launch_bounds__(256, 2)
gemm_hmma(const uint32_t* __restrict__ A, const uint32_t* __restrict__ B,
          int kstr, const float* __restrict__ bias, const float* __restrict__ wm2,
          const float* __restrict__ raw,
          const float* __restrict__ sw2, const float* __restrict__ sb2,
          const float* __restrict__ sw3, const float* __restrict__ sb3,
          const float* __restrict__ sw5, const float* __restrict__ sb5,
          const float* __restrict__ sw6, const float* __restrict__ sb6,
          float* __restrict__ sens)
{
    extern __shared__ char smem[];

    if (SENSOR && blockIdx.y >= 512) {
        sensor_block(smem, (blockIdx.y - 512) * 4 + blockIdx.x,
                     raw, sw2, sb2, sw3, sb3, sw5, sb5, sw6, sb6, sens);
        return;
    }

    const uint32_t ub = smem_u32(smem);
    float* biasS = (float*)(smem + BIAS_OFF);
    float* wm2s  = (float*)(smem + WM2_OFF);

    const int tid = threadIdx.x, wid = tid >> 5, lane = tid & 31;
    const int bn = blockIdx.x, bt = blockIdx.y;
    const int mw = (wid >> 1) * 32;
    const int nw = (wid & 1) * 64;

    if (tid < 128) biasS[tid] = bias[bn * 128 + tid];
    if (EPI == 1) {
        for (int i = tid; i < 128 * DX; i += 256) {
            int c = i / DX, m = i % DX;
            wm2s[c * 16 + m] = wm2[(size_t)(bn * 128 + c) * DX + m];
        }
    }

    auto issue_load = [&](int stage, int kc) {
        const uint32_t sb = ub + stage * STAGE_BYTES;
#pragma unroll
        for (int q = 0; q < 8; q++) {
            int i = tid + 256 * q;
            int t = i >> 10, r = (i >> 3) & 127, c = i & 7;
            const uint32_t* gp = t ? B : A;
            int grow = (t ? bn : bt) * 128 + r;
            const uint32_t* src = gp + (size_t)grow * kstr + kc * 32 + c * 4;
            uint32_t dst = sb + t * 16384 + r * 128 + ((c * 16) ^ ((r & 7) << 4));
            CP16(dst, src);
        }
        CP_COMMIT();
    };

    float acc[2][8][4];
#pragma unroll
    for (int f = 0; f < 2; f++)
#pragma unroll
        for (int g = 0; g < 8; g++)
#pragma unroll
            for (int e = 0; e < 4; e++) acc[f][g][e] = 0.f;

    issue_load(0, 0);
    if (KCHUNKS > 1) issue_load(1, 1);

#pragma unroll 1
    for (int kc = 0; kc < KCHUNKS; kc++) {
        if (kc + 2 < KCHUNKS) {
            issue_load((kc + 2) % 3, kc + 2);
            CP_WAITG(2);
        } else if (kc + 1 < KCHUNKS) {
            CP_WAITG(1);
        } else {
            CP_WAITG(0);
        }
        __syncthreads();

        const uint32_t sb = ub + (kc % 3) * STAGE_BYTES;
#pragma unroll
        for (int k16 = 0; k16 < 4; k16++) {
            uint32_t ah[2][4];
#pragma unroll
            for (int f = 0; f < 2; f++) {
                int mrow = mw + f * 16 + (lane & 15);
                int cb = k16 * 32 + ((lane >> 4) << 4);
                uint32_t off = mrow * 128 + (cb ^ ((mrow & 7) << 4));
                ldsm4(ah[f], sb + off);
            }
            uint32_t bh[4][4];
#pragma unroll
            for (int g = 0; g < 4; g++) {
                int nrow = nw + g * 16 + ((lane >> 4) << 3) + (lane & 7);
                int cb = k16 * 32 + (((lane >> 3) & 1) << 4);
                uint32_t off = nrow * 128 + (cb ^ ((nrow & 7) << 4));
                ldsm4(bh[g], sb + 16384 + off);
            }
#pragma unroll
            for (int f = 0; f < 2; f++)
#pragma unroll
                for (int g = 0; g < 4; g++) {
                    mma_f16(acc[f][2 * g],     ah[f], bh[g][0], bh[g][1]);
                    mma_f16(acc[f][2 * g + 1], ah[f], bh[g][2], bh[g][3]);
                }
        }
        __syncthreads();
    }

    if (EPI == 0) {
#pragma unroll
        for (int f = 0; f < 2; f++) {
            int row0 = bt * 128 + mw + f * 16 + (lane >> 2);
#pragma unroll
            for (int nf = 0; nf < 8; nf++) {
                int col = nw + nf * 8 + 2 * (lane & 3);
                float b0 = biasS[col], b1 = biasS[col + 1];
                float v0 = acc[f][nf][0] + b0, v1 = acc[f][nf][1] + b1;
                float v2 = acc[f][nf][2] + b0, v3 = acc[f][nf][3] + b1;
                v0 = v0 >= 0.f ? v0 : 0.01f * v0;
                v1 = v1 >= 0.f ? v1 : 0.01f * v1;
                v2 = v2 >= 0.f ? v2 : 0.01f * v2;
                v3 = v3 >= 0.f ? v3 : 0.01f * v3;
                int gcol = bn * 128 + col;
                g_h1[(size_t)row0 * 128 + gcol / 2]       = packA2(v0, v1);
                g_h1[(size_t)(row0 + 8) * 128 + gcol / 2] = packA2(v2, v3);
            }
        }
    } else {
        float proj[4][DX];
#pragma unroll
        for (int s2 = 0; s2 < 4; s2++)
#pragma unroll
            for (int m = 0; m < DX; m++) proj[s2][m] = 0.f;
#pragma unroll
        for (int f = 0; f < 2; f++)
#pragma unroll
            for (int nf = 0; nf < 8; nf++) {
                int col = nw + nf * 8 + 2 * (lane & 3);
#pragma unroll
                for (int e = 0; e < 2; e++) {
                    int c = col + e;
                    float b = biasS[c];
                    float v0 = acc[f][nf][e] + b;
                    float v1 = acc[f][nf][2 + e] + b;
                    v0 = v0 >= 0.f ? v0 : 0.01f * v0;
                    v1 = v1 >= 0.f ? v1 : 0.01f * v1;
                    const float* wr = wm2s + c * 16;
#pragma unroll
                    for (int m = 0; m < DX; m++) {
                        float wv = wr[m];
                        proj[2 * f][m]     += v0 * wv;
                        proj[2 * f + 1][m] += v1 * wv;
                    }
                }
            }
#pragma unroll
        for (int s2 = 0; s2 < 4; s2++)
#pragma unroll
            for (int m = 0; m < DX; m++) {
                proj[s2][m] += __shfl_xor_sync(0xFFFFFFFFu, proj[s2][m], 1);
                proj[s2][m] += __shfl_xor_sync(0xFFFFFFFFu, proj[s2][m], 2);
            }
        if ((lane & 3) == 0) {
            int slice = bn * 2 + (wid & 1);
#pragma unroll
            for (int s2 = 0; s2 < 4; s2++) {
                int row = bt * 128 + mw + (s2 >> 1) * 16 + (lane >> 2) + (s2 & 1) * 8;
                float* dst = g_part + ((size_t)slice * BE + row) * DX;
#pragma unroll
                for (int m = 0; m < DX; m++) dst[m] = proj[s2][m];
            }
        }
    }
}

// ---------------- EnKF per batch element ----------------
__global__ void __launch_bounds__(256)
enkf_kernel(const float* __restrict__ part, const float* __restrict__ pm_bm2,
            const float* __restrict__ sens,
            const float* __restrict__ on_w1, const float* __restrict__ on_b1,
            const float* __restrict__ on_w2, const float* __restrict__ on_b2,
            float* __restrict__ out1, float* __restrict__ out2,
            float* __restrict__ out3, float* __restrict__ out4,
            float* __restrict__ out5)
{
    const int b = blockIdx.x, tid = threadIdx.x;
    __shared__ float pred[ENS][DX], ez[ENS][DZ], Am[ENS][DX], corr[ENS][DX];
    __shared__ float sm[DX], zm[DZ], rdiag[DZ], hid[32];
    __shared__ float Mm[DX][DX], Km[DX][DZ], aug[DX][2 * DX], fac[DX];

    for (int i = tid; i < ENS * DX; i += 256) {
        int e = i / DX, j = i % DX;
        size_t row = (size_t)b * ENS + e;
        float p = pm_bm2[j];
#pragma unroll
        for (int q = 0; q < 8; q++) p += part[((size_t)q * BE + row) * DX + j];
        pred[e][j] = p;
    }
    for (int i = tid; i < ENS * DZ; i += 256) {
        int e = i / DZ, j = i % DZ;
        int src = (b * ENS + e) % BATCH;
        float v = sens[src * DZ + j];
        ez[e][j] = v;
        out5[(size_t)(b * ENS + e) * DZ + j] = v;
    }
    __syncthreads();
    if (tid < DX) {
        float s1 = 0.f, s2 = 0.f;
        for (int e = 0; e < ENS; e++) { s1 += pred[e][tid]; s2 += ez[e][tid]; }
        float m1 = s1 * (1.f / ENS), m2 = s2 * (1.f / ENS);
        sm[tid] = m1; zm[tid] = m2;
        out3[b * DX + tid] = m1;
        out4[b * DZ + tid] = m2;
    }
    __syncthreads();
    if (tid < 32) {
        float a = on_b1[tid];
        for (int i = 0; i < DZ; i++) a += zm[i] * on_w1[i * 32 + tid];
        hid[tid] = a > 0.f ? a : 0.f;
    }
    __syncthreads();
    if (tid < DZ) {
        float a = on_b2[tid];
        for (int j = 0; j < 32; j++) a += hid[j] * on_w2[j * DZ + tid];
        a += 0.001f;
        rdiag[tid] = a * a + 0.038729833f;
    }
    for (int i = tid; i < ENS * DX; i += 256)
        Am[i / DX][i % DX] = pred[i / DX][i % DX] - sm[i % DX];
    __syncthreads();
    if (tid < DX * DX) {
        int i = tid / DX, j = tid % DX;
        float s = 0.f;
        for (int e = 0; e < ENS; e++) s += Am[e][i] * Am[e][j];
        float m = s * (1.f / (ENS - 1));
        Mm[i][j] = m;
        aug[i][j] = m + (i == j ? rdiag[i] : 0.f);
        aug[i][DX + j] = (i == j) ? 1.f : 0.f;
    }
    __syncthreads();
    for (int p = 0; p < DX; p++) {
        float pv = aug[p][p];
        __syncthreads();
        if (tid < 2 * DX) aug[p][tid] *= (1.f / pv);
        if (tid < DX) fac[tid] = (tid == p) ? 0.f : aug[tid][p];
        __syncthreads();
        for (int t = tid; t < DX * 2 * DX; t += 256) {
            int rr = t / (2 * DX), c = t % (2 * DX);
            if (rr != p) aug[rr][c] -= fac[rr] * aug[p][c];
        }
        __syncthreads();
    }
    if (tid < DX * DX) {
        int i = tid / DX, j = tid % DX;
        float s = 0.f;
        for (int k = 0; k < DX; k++) s += Mm[i][k] * aug[k][DX + j];
        Km[i][j] = s;
    }
    __syncthreads();
    for (int t = tid; t < ENS * DX; t += 256) {
        int e = t / DX, i = t % DX;
        float s = pred[e][i];
        for (int j = 0; j < DZ; j++) s += Km[i][j] * (ez[e][j] - pred[e][j]);
        corr[e][i] = s;
        out1[(size_t)(b * ENS + e) * DX + i] = s;
    }
    __syncthreads();
    if (tid < DX) {
        float s = 0.f;
        for (int e = 0; e < ENS; e++) s += corr[e][tid];
        out2[b * DX + tid] = s * (1.f / ENS);
    }
}

// ---------------- launcher ----------------
extern "C" void kernel_launch(void* const* d_in, const int* in_sizes, int n_in,
                              void* d_out, int out_size)
{
    const float* raw    = (const float*)d_in[0];
    const float* sp     = (const float*)d_in[1];
    const float* pm_w1  = (const float*)d_in[2];
    const float* pm_b1  = (const float*)d_in[3];
    const float* pm_w3  = (const float*)d_in[4];
    const float* pm_b3  = (const float*)d_in[5];
    const float* pm_wm2 = (const float*)d_in[6];
    const float* pm_bm2 = (const float*)d_in[7];
    const float* sm_w2  = (const float*)d_in[8];
    const float* sm_b2  = (const float*)d_in[9];
    const float* sm_w3  = (const float*)d_in[10];
    const float* sm_b3  = (const float*)d_in[11];
    const float* sm_w5  = (const float*)d_in[12];
    const float* sm_b5  = (const float*)d_in[13];
    const float* sm_w6  = (const float*)d_in[14];
    const float* sm_b6  = (const float*)d_in[15];
    const float* on_w1  = (const float*)d_in[16];
    const float* on_b1  = (const float*)d_in[17];
    const float* on_w2  = (const float*)d_in[18];
    const float* on_b2  = (const float*)d_in[19];

    float* out = (float*)d_out;

    uint32_t *xp, *w1p, *w3p, *h1p;
    float *partp, *sensp;
    cudaGetSymbolAddress((void**)&xp,  g_x);
    cudaGetSymbolAddress((void**)&w1p, g_w1);
    cudaGetSymbolAddress((void**)&w3p, g_w3);
    cudaGetSymbolAddress((void**)&h1p, g_h1);
    cudaGetSymbolAddress((void**)&partp, g_part);
    cudaGetSymbolAddress((void**)&sensp, g_sens);

    cudaFuncSetAttribute(gemm_hmma<3, 0, 0>, cudaFuncAttributeMaxDynamicSharedMemorySize, DYN_SMEM);
    cudaFuncSetAttribute(gemm_hmma<4, 1, 1>, cudaFuncAttributeMaxDynamicSharedMemorySize, DYN_SMEM);

    prep_w_kernel<<<(256 * 96 + 512 * 128 + 255) / 256, 256>>>(pm_w1, pm_w3);
    prep_x_kernel<<<BE * 96 / 256, 256>>>(sp);

    // GEMM A: h1 = leaky(x @ w1 + b1)  [BE x 256], K=192 (padded)
    gemm_hmma<3, 0, 0><<<dim3(2, BE / 128), 256, DYN_SMEM>>>(
        xp, w1p, 96, pm_b1, nullptr,
        nullptr, nullptr, nullptr, nullptr, nullptr,
        nullptr, nullptr, nullptr, nullptr, nullptr);
    // GEMM B + sensor co-launch: bt<512 = GEMM, bt>=512 (256 blocks) = sensor MLP
    gemm_hmma<4, 1, 1><<<dim3(4, BE / 128 + 64), 256, DYN_SMEM>>>(
        h1p, w3p, 128, pm_b3, pm_wm2,
        raw, sm_w2, sm_b2, sm_w3, sm_b3, sm_w5, sm_b5, sm_w6, sm_b6, sensp);

    enkf_kernel<<<BATCH, 256>>>(partp, pm_bm2, sensp, on_w1, on_b1, on_w2, on_b2,
                                out + O1_OFF, out + O2_OFF, out + O3_OFF,
                                out + O4_OFF, out + O5_OFF);
}

// round 17
// speedup vs baseline: 1.5303x; 1.0300x over previous
#include <cuda_runtime.h>
#include <cuda_fp16.h>
#include <cstdint>

#define BATCH 2048
#define ENS   32
#define DX    14
#define DZ    14
#define PM_IN 140
#define SM_IN 220
#define BE    (BATCH * ENS)

#define O1_OFF 0
#define O2_OFF (BATCH * ENS * DX)
#define O3_OFF (O2_OFF + BATCH * DX)
#define O4_OFF (O3_OFF + BATCH * DX)
#define O5_OFF (O4_OFF + BATCH * DZ)

// smem layout (per CTA): 3 stages x 32KB tiles, then bias, then wm2 slice
#define STAGE_BYTES 32768
#define BIAS_OFF    98304
#define WM2_OFF     98816
#define DYN_SMEM    107008

// ---------------- scratch globals (uint32 = packed fp16 pair) ----------------
__device__ uint32_t g_x [(size_t)BE * 96];     // x   fp16 [BE][192]
__device__ uint32_t g_w1[256 * 96];            // w1^T fp16 [256][192]
__device__ uint32_t g_w3[512 * 128];           // w3^T fp16 [512][256]
__device__ uint32_t g_h1[(size_t)BE * 128];    // h1  fp16 [BE][256]
__device__ float    g_part[(size_t)8 * BE * DX];   // 8 partial slices
__device__ float    g_sens[BATCH * DZ];

// ---------------- helpers ----------------
__device__ __forceinline__ uint32_t smem_u32(const void* p) {
    uint32_t a;
    asm("{ .reg .u64 t; cvta.to.shared.u64 t, %1; cvt.u32.u64 %0, t; }" : "=r"(a) : "l"(p));
    return a;
}
#define CP16(d, s) asm volatile("cp.async.cg.shared.global [%0], [%1], 16;" :: "r"(d), "l"(s))
#define CP_COMMIT() asm volatile("cp.async.commit_group;")
#define CP_WAITG(n) asm volatile("cp.async.wait_group %0;" :: "n"(n) : "memory")

__device__ __forceinline__ void ldsm4(uint32_t (&r)[4], uint32_t addr) {
    asm volatile("ldmatrix.sync.aligned.m8n8.x4.shared.b16 {%0,%1,%2,%3}, [%4];"
                 : "=r"(r[0]), "=r"(r[1]), "=r"(r[2]), "=r"(r[3]) : "r"(addr));
}
__device__ __forceinline__ void mma_f16(float (&d)[4], const uint32_t (&a)[4],
                                        uint32_t b0, uint32_t b1) {
    asm volatile(
        "mma.sync.aligned.m16n8k16.row.col.f32.f16.f16.f32 "
        "{%0,%1,%2,%3}, {%4,%5,%6,%7}, {%8,%9}, {%0,%1,%2,%3};"
        : "+f"(d[0]), "+f"(d[1]), "+f"(d[2]), "+f"(d[3])
        : "r"(a[0]), "r"(a[1]), "r"(a[2]), "r"(a[3]), "r"(b0), "r"(b1));
}
__device__ __forceinline__ uint32_t packA2(float v0, float v1) {
    __half h0 = __float2half_rn(v0), h1 = __float2half_rn(v1);
    return (uint32_t)__half_as_ushort(h0) | ((uint32_t)__half_as_ushort(h1) << 16);
}

// ---------------- prep: x -> fp16, K padded to 192 ----------------
__global__ void __launch_bounds__(256)
prep_x_kernel(const float* __restrict__ x)
{
    int idx = blockIdx.x * 256 + threadIdx.x;   // BE*96
    int row = idx / 96, p = idx % 96, k = 2 * p;
    float v0 = (k < PM_IN) ? x[(size_t)row * PM_IN + k] : 0.f;
    float v1 = (k + 1 < PM_IN) ? x[(size_t)row * PM_IN + k + 1] : 0.f;
    g_x[(size_t)row * 96 + p] = packA2(v0, v1);
}

// ---------------- prep: weights transposed -> fp16 ----------------
__global__ void __launch_bounds__(256)
prep_w_kernel(const float* __restrict__ w1, const float* __restrict__ w3)
{
    int idx = blockIdx.x * 256 + threadIdx.x;
    if (idx < 256 * 96) {                        // w1 [140][256] -> [256][192]
        int n = idx / 96, p = idx % 96, k = 2 * p;
        float v0 = (k < PM_IN) ? w1[(size_t)k * 256 + n] : 0.f;
        float v1 = (k + 1 < PM_IN) ? w1[(size_t)(k + 1) * 256 + n] : 0.f;
        g_w1[idx] = packA2(v0, v1);
    } else if (idx < 256 * 96 + 512 * 128) {     // w3 [256][512] -> [512][256]
        int i2 = idx - 256 * 96;
        int n = i2 / 128, p = i2 % 128, k = 2 * p;
        g_w3[i2] = packA2(w3[(size_t)k * 512 + n], w3[(size_t)(k + 1) * 512 + n]);
    }
}

// ---------------- sensor MLP as a device block (8 rows/block) -------------
__device__ void sensor_block(char* smem, int sblk,
                             const float* __restrict__ raw,
                             const float* __restrict__ w2, const float* __restrict__ b2,
                             const float* __restrict__ w3, const float* __restrict__ b3,
                             const float* __restrict__ w5, const float* __restrict__ b5,
                             const float* __restrict__ w6, const float* __restrict__ b6,
                             float* __restrict__ sens)
{
    float* bufA = (float*)smem;              // 8*256 floats (input stride 220, then h2 stride 256)
    float* h1s  = (float*)(smem + 8192);     // 8*256
    float* h3s  = (float*)(smem + 16384);    // 8*64
    const int tid = threadIdx.x;
    const int row0 = sblk * 8;

    for (int i = tid; i < 8 * SM_IN; i += 256) {
        int r = i / SM_IN, k = i % SM_IN;
        bufA[r * SM_IN + k] = raw[(size_t)(row0 + r) * SM_IN + k];
    }
    __syncthreads();

    float acc[8];
    {   // layer 1: 220 -> 256, leaky
#pragma unroll
        for (int r = 0; r < 8; r++) acc[r] = b2[tid];
#pragma unroll 4
        for (int k = 0; k < SM_IN; k++) {
            float w = w2[k * 256 + tid];
#pragma unroll
            for (int r = 0; r < 8; r++) acc[r] += bufA[r * SM_IN + k] * w;
        }
#pragma unroll
        for (int r = 0; r < 8; r++)
            h1s[r * 256 + tid] = acc[r] >= 0.f ? acc[r] : 0.01f * acc[r];
    }
    __syncthreads();
    {   // layer 2: 256 -> 256, leaky -> bufA (stride 256)
#pragma unroll
        for (int r = 0; r < 8; r++) acc[r] = b3[tid];
#pragma unroll 4
        for (int k = 0; k < 256; k++) {
            float w = w3[k * 256 + tid];
#pragma unroll
            for (int r = 0; r < 8; r++) acc[r] += h1s[r * 256 + k] * w;
        }
        __syncthreads();
#pragma unroll
        for (int r = 0; r < 8; r++)
            bufA[r * 256 + tid] = acc[r] >= 0.f ? acc[r] : 0.01f * acc[r];
    }
    __syncthreads();
    {   // layer 3: 256 -> 64, leaky. 256 thr = 64 cols x 4 row-groups x 2 rows
        int col = tid & 63, rg = tid >> 6;
        float a0 = b5[col], a1 = a0;
        int r0 = rg * 2, r1 = rg * 2 + 1;
#pragma unroll 4
        for (int k = 0; k < 256; k++) {
            float w = w5[k * 64 + col];
            a0 += bufA[r0 * 256 + k] * w;
            a1 += bufA[r1 * 256 + k] * w;
        }
        h3s[r0 * 64 + col] = a0 >= 0.f ? a0 : 0.01f * a0;
        h3s[r1 * 64 + col] = a1 >= 0.f ? a1 : 0.01f * a1;
    }
    __syncthreads();
    if (tid < 8 * DZ) {   // layer 4: 64 -> 14, linear. 112 thr = 14 cols x 8 rows
        int col = tid % DZ, r = tid / DZ;
        float a = b6[col];
#pragma unroll 4
        for (int k = 0; k < 64; k++)
            a += h3s[r * 64 + k] * w6[k * DZ + col];
        sens[(size_t)(row0 + r) * DZ + col] = a;
    }
}

// ---------------- HMMA fp16 GEMM: 8 warps, 2 CTAs/SM, 3-stage pipeline -----
// CTA tile 128x128, BK=64, 8 warps (4m x 2n), warp tile 32x64.  (R10 proven)
// SENSOR=1 (EPI=1): blocks with blockIdx.y < 64 run the sensor MLP (front of
// grid -> scheduled in wave 0, overlapping the gemm waves instead of tailing).
template <int KCHUNKS, int EPI, int SENSOR>
__global__ void __launch_bounds__(256, 2)
gemm_hmma(const uint32_t* __restrict__ A, const uint32_t* __restrict__ B,
          int kstr, const float* __restrict__ bias, const float* __restrict__ wm2,
          const float* __restrict__ raw,
          const float* __restrict__ sw2, const float* __restrict__ sb2,
          const float* __restrict__ sw3, const float* __restrict__ sb3,
          const float* __restrict__ sw5, const float* __restrict__ sb5,
          const float* __restrict__ sw6, const float* __restrict__ sb6,
          float* __restrict__ sens)
{
    extern __shared__ char smem[];

    if (SENSOR && blockIdx.y < 64) {
        sensor_block(smem, blockIdx.y * 4 + blockIdx.x,
                     raw, sw2, sb2, sw3, sb3, sw5, sb5, sw6, sb6, sens);
        return;
    }

    const uint32_t ub = smem_u32(smem);
    float* biasS = (float*)(smem + BIAS_OFF);
    float* wm2s  = (float*)(smem + WM2_OFF);

    const int tid = threadIdx.x, wid = tid >> 5, lane = tid & 31;
    const int bn = blockIdx.x;
    const int bt = SENSOR ? (blockIdx.y - 64) : blockIdx.y;
    const int mw = (wid >> 1) * 32;
    const int nw = (wid & 1) * 64;

    if (tid < 128) biasS[tid] = bias[bn * 128 + tid];
    if (EPI == 1) {
        for (int i = tid; i < 128 * DX; i += 256) {
            int c = i / DX, m = i % DX;
            wm2s[c * 16 + m] = wm2[(size_t)(bn * 128 + c) * DX + m];
        }
    }

    auto issue_load = [&](int stage, int kc) {
        const uint32_t sb = ub + stage * STAGE_BYTES;
#pragma unroll
        for (int q = 0; q < 8; q++) {
            int i = tid + 256 * q;
            int t = i >> 10, r = (i >> 3) & 127, c = i & 7;
            const uint32_t* gp = t ? B : A;
            int grow = (t ? bn : bt) * 128 + r;
            const uint32_t* src = gp + (size_t)grow * kstr + kc * 32 + c * 4;
            uint32_t dst = sb + t * 16384 + r * 128 + ((c * 16) ^ ((r & 7) << 4));
            CP16(dst, src);
        }
        CP_COMMIT();
    };

    float acc[2][8][4];
#pragma unroll
    for (int f = 0; f < 2; f++)
#pragma unroll
        for (int g = 0; g < 8; g++)
#pragma unroll
            for (int e = 0; e < 4; e++) acc[f][g][e] = 0.f;

    issue_load(0, 0);
    if (KCHUNKS > 1) issue_load(1, 1);

#pragma unroll 1
    for (int kc = 0; kc < KCHUNKS; kc++) {
        if (kc + 2 < KCHUNKS) {
            issue_load((kc + 2) % 3, kc + 2);
            CP_WAITG(2);
        } else if (kc + 1 < KCHUNKS) {
            CP_WAITG(1);
        } else {
            CP_WAITG(0);
        }
        __syncthreads();

        const uint32_t sb = ub + (kc % 3) * STAGE_BYTES;
#pragma unroll
        for (int k16 = 0; k16 < 4; k16++) {
            uint32_t ah[2][4];
#pragma unroll
            for (int f = 0; f < 2; f++) {
                int mrow = mw + f * 16 + (lane & 15);
                int cb = k16 * 32 + ((lane >> 4) << 4);
                uint32_t off = mrow * 128 + (cb ^ ((mrow & 7) << 4));
                ldsm4(ah[f], sb + off);
            }
            uint32_t bh[4][4];
#pragma unroll
            for (int g = 0; g < 4; g++) {
                int nrow = nw + g * 16 + ((lane >> 4) << 3) + (lane & 7);
                int cb = k16 * 32 + (((lane >> 3) & 1) << 4);
                uint32_t off = nrow * 128 + (cb ^ ((nrow & 7) << 4));
                ldsm4(bh[g], sb + 16384 + off);
            }
#pragma unroll
            for (int f = 0; f < 2; f++)
#pragma unroll
                for (int g = 0; g < 4; g++) {
                    mma_f16(acc[f][2 * g],     ah[f], bh[g][0], bh[g][1]);
                    mma_f16(acc[f][2 * g + 1], ah[f], bh[g][2], bh[g][3]);
                }
        }
        __syncthreads();
    }

    if (EPI == 0) {
#pragma unroll
        for (int f = 0; f < 2; f++) {
            int row0 = bt * 128 + mw + f * 16 + (lane >> 2);
#pragma unroll
            for (int nf = 0; nf < 8; nf++) {
                int col = nw + nf * 8 + 2 * (lane & 3);
                float b0 = biasS[col], b1 = biasS[col + 1];
                float v0 = acc[f][nf][0] + b0, v1 = acc[f][nf][1] + b1;
                float v2 = acc[f][nf][2] + b0, v3 = acc[f][nf][3] + b1;
                v0 = v0 >= 0.f ? v0 : 0.01f * v0;
                v1 = v1 >= 0.f ? v1 : 0.01f * v1;
                v2 = v2 >= 0.f ? v2 : 0.01f * v2;
                v3 = v3 >= 0.f ? v3 : 0.01f * v3;
                int gcol = bn * 128 + col;
                g_h1[(size_t)row0 * 128 + gcol / 2]       = packA2(v0, v1);
                g_h1[(size_t)(row0 + 8) * 128 + gcol / 2] = packA2(v2, v3);
            }
        }
    } else {
        float proj[4][DX];
#pragma unroll
        for (int s2 = 0; s2 < 4; s2++)
#pragma unroll
            for (int m = 0; m < DX; m++) proj[s2][m] = 0.f;
#pragma unroll
        for (int f = 0; f < 2; f++)
#pragma unroll
            for (int nf = 0; nf < 8; nf++) {
                int col = nw + nf * 8 + 2 * (lane & 3);
#pragma unroll
                for (int e = 0; e < 2; e++) {
                    int c = col + e;
                    float b = biasS[c];
                    float v0 = acc[f][nf][e] + b;
                    float v1 = acc[f][nf][2 + e] + b;
                    v0 = v0 >= 0.f ? v0 : 0.01f * v0;
                    v1 = v1 >= 0.f ? v1 : 0.01f * v1;
                    const float* wr = wm2s + c * 16;
#pragma unroll
                    for (int m = 0; m < DX; m++) {
                        float wv = wr[m];
                        proj[2 * f][m]     += v0 * wv;
                        proj[2 * f + 1][m] += v1 * wv;
                    }
                }
            }
#pragma unroll
        for (int s2 = 0; s2 < 4; s2++)
#pragma unroll
            for (int m = 0; m < DX; m++) {
                proj[s2][m] += __shfl_xor_sync(0xFFFFFFFFu, proj[s2][m], 1);
                proj[s2][m] += __shfl_xor_sync(0xFFFFFFFFu, proj[s2][m], 2);
            }
        if ((lane & 3) == 0) {
            int slice = bn * 2 + (wid & 1);
#pragma unroll
            for (int s2 = 0; s2 < 4; s2++) {
                int row = bt * 128 + mw + (s2 >> 1) * 16 + (lane >> 2) + (s2 & 1) * 8;
                float* dst = g_part + ((size_t)slice * BE + row) * DX;
#pragma unroll
                for (int m = 0; m < DX; m++) dst[m] = proj[s2][m];
            }
        }
    }
}

// ---------------- EnKF per batch element ----------------
__global__ void __launch_bounds__(256)
enkf_kernel(const float* __restrict__ part, const float* __restrict__ pm_bm2,
            const float* __restrict__ sens,
            const float* __restrict__ on_w1, const float* __restrict__ on_b1,
            const float* __restrict__ on_w2, const float* __restrict__ on_b2,
            float* __restrict__ out1, float* __restrict__ out2,
            float* __restrict__ out3, float* __restrict__ out4,
            float* __restrict__ out5)
{
    const int b = blockIdx.x, tid = threadIdx.x;
    __shared__ float pred[ENS][DX], ez[ENS][DZ], Am[ENS][DX], corr[ENS][DX];
    __shared__ float sm[DX], zm[DZ], rdiag[DZ], hid[32];
    __shared__ float Mm[DX][DX], Km[DX][DZ], aug[DX][2 * DX], fac[DX];

    for (int i = tid; i < ENS * DX; i += 256) {
        int e = i / DX, j = i % DX;
        size_t row = (size_t)b * ENS + e;
        float p = pm_bm2[j];
#pragma unroll
        for (int q = 0; q < 8; q++) p += part[((size_t)q * BE + row) * DX + j];
        pred[e][j] = p;
    }
    for (int i = tid; i < ENS * DZ; i += 256) {
        int e = i / DZ, j = i % DZ;
        int src = (b * ENS + e) % BATCH;
        float v = sens[src * DZ + j];
        ez[e][j] = v;
        out5[(size_t)(b * ENS + e) * DZ + j] = v;
    }
    __syncthreads();
    if (tid < DX) {
        float s1 = 0.f, s2 = 0.f;
        for (int e = 0; e < ENS; e++) { s1 += pred[e][tid]; s2 += ez[e][tid]; }
        float m1 = s1 * (1.f / ENS), m2 = s2 * (1.f / ENS);
        sm[tid] = m1; zm[tid] = m2;
        out3[b * DX + tid] = m1;
        out4[b * DZ + tid] = m2;
    }
    __syncthreads();
    if (tid < 32) {
        float a = on_b1[tid];
        for (int i = 0; i < DZ; i++) a += zm[i] * on_w1[i * 32 + tid];
        hid[tid] = a > 0.f ? a : 0.f;
    }
    __syncthreads();
    if (tid < DZ) {
        float a = on_b2[tid];
        for (int j = 0; j < 32; j++) a += hid[j] * on_w2[j * DZ + tid];
        a += 0.001f;
        rdiag[tid] = a * a + 0.038729833f;
    }
    for (int i = tid; i < ENS * DX; i += 256)
        Am[i / DX][i % DX] = pred[i / DX][i % DX] - sm[i % DX];
    __syncthreads();
    if (tid < DX * DX) {
        int i = tid / DX, j = tid % DX;
        float s = 0.f;
        for (int e = 0; e < ENS; e++) s += Am[e][i] * Am[e][j];
        float m = s * (1.f / (ENS - 1));
        Mm[i][j] = m;
        aug[i][j] = m + (i == j ? rdiag[i] : 0.f);
        aug[i][DX + j] = (i == j) ? 1.f : 0.f;
    }
    __syncthreads();
    for (int p = 0; p < DX; p++) {
        float pv = aug[p][p];
        __syncthreads();
        if (tid < 2 * DX) aug[p][tid] *= (1.f / pv);
        if (tid < DX) fac[tid] = (tid == p) ? 0.f : aug[tid][p];
        __syncthreads();
        for (int t = tid; t < DX * 2 * DX; t += 256) {
            int rr = t / (2 * DX), c = t % (2 * DX);
            if (rr != p) aug[rr][c] -= fac[rr] * aug[p][c];
        }
        __syncthreads();
    }
    if (tid < DX * DX) {
        int i = tid / DX, j = tid % DX;
        float s = 0.f;
        for (int k = 0; k < DX; k++) s += Mm[i][k] * aug[k][DX + j];
        Km[i][j] = s;
    }
    __syncthreads();
    for (int t = tid; t < ENS * DX; t += 256) {
        int e = t / DX, i = t % DX;
        float s = pred[e][i];
        for (int j = 0; j < DZ; j++) s += Km[i][j] * (ez[e][j] - pred[e][j]);
        corr[e][i] = s;
        out1[(size_t)(b * ENS + e) * DX + i] = s;
    }
    __syncthreads();
    if (tid < DX) {
        float s = 0.f;
        for (int e = 0; e < ENS; e++) s += corr[e][tid];
        out2[b * DX + tid] = s * (1.f / ENS);
    }
}

// ---------------- launcher ----------------
extern "C" void kernel_launch(void* const* d_in, const int* in_sizes, int n_in,
                              void* d_out, int out_size)
{
    const float* raw    = (const float*)d_in[0];
    const float* sp     = (const float*)d_in[1];
    const float* pm_w1  = (const float*)d_in[2];
    const float* pm_b1  = (const float*)d_in[3];
    const float* pm_w3  = (const float*)d_in[4];
    const float* pm_b3  = (const float*)d_in[5];
    const float* pm_wm2 = (const float*)d_in[6];
    const float* pm_bm2 = (const float*)d_in[7];
    const float* sm_w2  = (const float*)d_in[8];
    const float* sm_b2  = (const float*)d_in[9];
    const float* sm_w3  = (const float*)d_in[10];
    const float* sm_b3  = (const float*)d_in[11];
    const float* sm_w5  = (const float*)d_in[12];
    const float* sm_b5  = (const float*)d_in[13];
    const float* sm_w6  = (const float*)d_in[14];
    const float* sm_b6  = (const float*)d_in[15];
    const float* on_w1  = (const float*)d_in[16];
    const float* on_b1  = (const float*)d_in[17];
    const float* on_w2  = (const float*)d_in[18];
    const float* on_b2  = (const float*)d_in[19];

    float* out = (float*)d_out;

    uint32_t *xp, *w1p, *w3p, *h1p;
    float *partp, *sensp;
    cudaGetSymbolAddress((void**)&xp,  g_x);
    cudaGetSymbolAddress((void**)&w1p, g_w1);
    cudaGetSymbolAddress((void**)&w3p, g_w3);
    cudaGetSymbolAddress((void**)&h1p, g_h1);
    cudaGetSymbolAddress((void**)&partp, g_part);
    cudaGetSymbolAddress((void**)&sensp, g_sens);

    cudaFuncSetAttribute(gemm_hmma<3, 0, 0>, cudaFuncAttributeMaxDynamicSharedMemorySize, DYN_SMEM);
    cudaFuncSetAttribute(gemm_hmma<4, 1, 1>, cudaFuncAttributeMaxDynamicSharedMemorySize, DYN_SMEM);

    prep_w_kernel<<<(256 * 96 + 512 * 128 + 255) / 256, 256>>>(pm_w1, pm_w3);
    prep_x_kernel<<<BE * 96 / 256, 256>>>(sp);

    // GEMM A: h1 = leaky(x @ w1 + b1)  [BE x 256], K=192 (padded)
    gemm_hmma<3, 0, 0><<<dim3(2, BE / 128), 256, DYN_SMEM>>>(
        xp, w1p, 96, pm_b1, nullptr,
        nullptr, nullptr, nullptr, nullptr, nullptr,
        nullptr, nullptr, nullptr, nullptr, nullptr);
    // GEMM B + sensor co-launch: bt<64 = sensor MLP (front of grid -> wave 0),
    // bt>=64 = GEMM (bt-64).
    gemm_hmma<4, 1, 1><<<dim3(4, BE / 128 + 64), 256, DYN_SMEM>>>(
        h1p, w3p, 128, pm_b3, pm_wm2,
        raw, sm_w2, sm_b2, sm_w3, sm_b3, sm_w5, sm_b5, sm_w6, sm_b6, sensp);

    enkf_kernel<<<BATCH, 256>>>(partp, pm_bm2, sensp, on_w1, on_b1, on_w2, on_b2,
                                out + O1_OFF, out + O2_OFF, out + O3_OFF,
                                out + O4_OFF, out + O5_OFF);
}